// round 7
// baseline (speedup 1.0000x reference)
#include <cuda_runtime.h>
#include <cuda_bf16.h>
#include <math.h>
#include <stdint.h>

#define BB 32
#define SS 1024
#define CC 384
#define HH 384
#define MAX_OUT_T 3072
#define M_TOTAL (BB*SS)          // 32768
#define KDIM (3*CC)              // 1152
#define PRED_OFFSET ((size_t)BB*MAX_OUT_T*CC)

// ---------------- scratch (static device globals: allocation-free) ----------
__device__ __nv_bfloat16 g_xb [(size_t)M_TOTAL*CC];
__device__ __nv_bfloat16 g_h1b[(size_t)M_TOTAL*HH];
__device__ __nv_bfloat16 g_wt1[(size_t)HH*KDIM];
__device__ __nv_bfloat16 g_wt2[(size_t)HH*KDIM];
__device__ float g_tmp1[(size_t)M_TOTAL*HH];
__device__ float g_tmp2[(size_t)M_TOTAL*HH];
__device__ int   g_cum[BB*SS];

// ---------------- PTX helpers (baseline PTX only) ----------------------------
__device__ __forceinline__ uint32_t smem_u32(const void* p) {
    uint32_t a;
    asm("{ .reg .u64 t; cvta.to.shared.u64 t, %1; cvt.u32.u64 %0, t; }" : "=r"(a) : "l"(p));
    return a;
}
__device__ __forceinline__ void cp_async16(uint32_t saddr, const void* gptr, uint32_t sz) {
    asm volatile("cp.async.cg.shared.global [%0], [%1], 16, %2;"
                 :: "r"(saddr), "l"(gptr), "r"(sz) : "memory");
}
__device__ __forceinline__ void cp_commit() {
    asm volatile("cp.async.commit_group;" ::: "memory");
}
template <int N>
__device__ __forceinline__ void cp_wait() {
    asm volatile("cp.async.wait_group %0;" :: "n"(N) : "memory");
}
__device__ __forceinline__ void ldmatrix_x4(uint32_t& r0, uint32_t& r1, uint32_t& r2,
                                            uint32_t& r3, uint32_t addr) {
    asm volatile("ldmatrix.sync.aligned.m8n8.x4.shared.b16 {%0,%1,%2,%3}, [%4];"
                 : "=r"(r0), "=r"(r1), "=r"(r2), "=r"(r3) : "r"(addr));
}
__device__ __forceinline__ void mma_16816(float& d0, float& d1, float& d2, float& d3,
                                          uint32_t a0, uint32_t a1, uint32_t a2, uint32_t a3,
                                          uint32_t b0, uint32_t b1) {
    asm volatile("mma.sync.aligned.m16n8k16.row.col.f32.bf16.bf16.f32 "
                 "{%0,%1,%2,%3}, {%4,%5,%6,%7}, {%8,%9}, {%0,%1,%2,%3};"
                 : "+f"(d0), "+f"(d1), "+f"(d2), "+f"(d3)
                 : "r"(a0), "r"(a1), "r"(a2), "r"(a3), "r"(b0), "r"(b1));
}

// ---------------------------------------------------------------------------
// Conv-as-GEMM on tensor cores (mma.sync bf16), 3-stage cp.async pipeline.
// CTA tile 128x128; 8 warps 2(m) x 4(n); warp tile 64x32.
// ---------------------------------------------------------------------------
#define NSTEPS 18
#define TILE_B 16384                       // 128 rows x 128 bytes
#define GEMM_SMEM (6*TILE_B)               // 3 stages x (A,B)

__global__ __launch_bounds__(256, 2)
void conv_gemm_mma(const __nv_bfloat16* __restrict__ A,
                   const __nv_bfloat16* __restrict__ Wt,
                   const float* __restrict__ bias,
                   float* __restrict__ out)
{
    extern __shared__ __align__(1024) char smem[];
    const uint32_t sbase = smem_u32(smem);
    const int tid  = threadIdx.x;
    const int wid  = tid >> 5;
    const int lane = tid & 31;
    const int warp_m = wid & 1;
    const int warp_n = wid >> 1;
    const int n0 = blockIdx.x * 128;
    const int m0 = blockIdx.y * 128;

    const int lrow = tid >> 3;              // 0..31 (+32*i)
    const int lcx  = (tid & 7) * 16;

    auto load_tiles = [&](int step, int stage) {
        const uint32_t abase = sbase + (uint32_t)stage * 2 * TILE_B;
        const uint32_t bbase = abase + TILE_B;
        const int k  = step / 6;
        const int c0 = (step - k * 6) * 64;
#pragma unroll
        for (int i = 0; i < 4; i++) {
            const int row = lrow + 32 * i;
            uint32_t off = (uint32_t)(row * 128 + lcx);
            uint32_t sw  = off ^ ((off >> 3) & 0x70);
            const int gm  = m0 + row;
            const int ss  = (gm & (SS - 1)) + k - 1;
            const bool valid = (ss >= 0) && (ss < SS);
            const char* gpa = (const char*)A + ((size_t)(gm + k - 1) * CC + c0) * 2 + lcx;
            if (!valid) gpa = (const char*)A;
            cp_async16(abase + sw, gpa, valid ? 16u : 0u);
            const char* gpb = (const char*)Wt + ((size_t)(n0 + row) * KDIM + step * 64) * 2 + lcx;
            cp_async16(bbase + sw, gpb, 16u);
        }
    };

    float acc[4][4][4];
#pragma unroll
    for (int i = 0; i < 4; i++)
#pragma unroll
        for (int j = 0; j < 4; j++)
#pragma unroll
            for (int q = 0; q < 4; q++) acc[i][j][q] = 0.f;

    const int fr_row = ((lane >> 3) & 1) * 8 + (lane & 7);
    const int fr_kb  = (lane >> 4) * 16;
    const uint32_t cxor = (uint32_t)((fr_row & 7) << 4);
    const uint32_t a_row_base = (uint32_t)((warp_m * 64 + fr_row) * 128);
    const uint32_t b_row_base = (uint32_t)((warp_n * 32 + fr_row) * 128);

    load_tiles(0, 0); cp_commit();
    load_tiles(1, 1); cp_commit();

    int stage = 0;
    for (int step = 0; step < NSTEPS; ++step) {
        cp_wait<1>();
        __syncthreads();

        const uint32_t sa = sbase + (uint32_t)stage * 2 * TILE_B;
        const uint32_t sb = sa + TILE_B;

        // ---- hoist ALL B fragments first (LDSM issue ASAP after barrier) ----
        uint32_t ball[4][2][4];
#pragma unroll
        for (int ks = 0; ks < 4; ks++) {
            const uint32_t col = ((uint32_t)(ks * 32 + fr_kb)) ^ cxor;
#pragma unroll
            for (int nt = 0; nt < 2; nt++) {
                const uint32_t addr = sb + b_row_base + (uint32_t)(nt * 2048) + col;
                ldmatrix_x4(ball[ks][nt][0], ball[ks][nt][1], ball[ks][nt][2], ball[ks][nt][3], addr);
            }
        }

        // prefetch step+2 into the stage we just vacated (issued while the
        // B-hoist LDSMs are in flight, so it doesn't delay compute startup)
        {
            const int pf = stage + 2 - ((stage + 2 >= 3) ? 3 : 0);
            if (step + 2 < NSTEPS) load_tiles(step + 2, pf);
            cp_commit();
        }

#pragma unroll
        for (int ks = 0; ks < 4; ks++) {
            const uint32_t col = ((uint32_t)(ks * 32 + fr_kb)) ^ cxor;
            uint32_t a[4][4];
#pragma unroll
            for (int mt = 0; mt < 4; mt++) {
                const uint32_t addr = sa + a_row_base + (uint32_t)(mt * 2048) + col;
                ldmatrix_x4(a[mt][0], a[mt][1], a[mt][2], a[mt][3], addr);
            }
#pragma unroll
            for (int mt = 0; mt < 4; mt++)
#pragma unroll
                for (int nt = 0; nt < 2; nt++)
#pragma unroll
                    for (int h = 0; h < 2; h++) {
                        const int j = nt * 2 + h;
                        mma_16816(acc[mt][j][0], acc[mt][j][1], acc[mt][j][2], acc[mt][j][3],
                                  a[mt][0], a[mt][1], a[mt][2], a[mt][3],
                                  ball[ks][nt][h], ball[ks][nt][2 + h]);
                    }
        }
        stage = (stage == 2) ? 0 : stage + 1;
    }

    const int g = lane >> 2;
    const int t = lane & 3;
#pragma unroll
    for (int mt = 0; mt < 4; mt++) {
        const int row0 = m0 + warp_m * 64 + mt * 16 + g;
#pragma unroll
        for (int j = 0; j < 4; j++) {
            const int col = n0 + warp_n * 32 + j * 8 + t * 2;
            const float2 bv = *(const float2*)(bias + col);
            float2 o0 = make_float2(acc[mt][j][0] + bv.x, acc[mt][j][1] + bv.y);
            float2 o1 = make_float2(acc[mt][j][2] + bv.x, acc[mt][j][3] + bv.y);
            *(float2*)(out + (size_t)row0 * HH + col)       = o0;
            *(float2*)(out + (size_t)(row0 + 8) * HH + col) = o1;
        }
    }
}

// ---------------------------------------------------------------------------
// Warp-per-row LayerNorm + ReLU -> bf16.
// ---------------------------------------------------------------------------
__global__ __launch_bounds__(256)
void ln_relu_bf16(const float* __restrict__ in, const float* __restrict__ g,
                  const float* __restrict__ beta, __nv_bfloat16* __restrict__ outb)
{
    const int row  = (blockIdx.x * 256 + threadIdx.x) >> 5;
    const int lane = threadIdx.x & 31;
    const float4* p = (const float4*)(in + (size_t)row * HH);

    float4 v[3];
    float s = 0.f, sq = 0.f;
#pragma unroll
    for (int i = 0; i < 3; i++) {
        v[i] = p[lane + 32 * i];
        s  += v[i].x + v[i].y + v[i].z + v[i].w;
        sq += v[i].x * v[i].x + v[i].y * v[i].y + v[i].z * v[i].z + v[i].w * v[i].w;
    }
#pragma unroll
    for (int off = 16; off > 0; off >>= 1) {
        s  += __shfl_xor_sync(0xffffffffu, s,  off);
        sq += __shfl_xor_sync(0xffffffffu, sq, off);
    }
    const float mu = s * (1.f / HH);
    const float rs = rsqrtf(sq * (1.f / HH) - mu * mu + 1e-5f);

    __nv_bfloat16* op = outb + (size_t)row * HH;
#pragma unroll
    for (int i = 0; i < 3; i++) {
        const int c = (lane + 32 * i) * 4;
        const float4 gv = *(const float4*)(g + c);
        const float4 bv = *(const float4*)(beta + c);
        float o0 = fmaxf(0.f, (v[i].x - mu) * rs * gv.x + bv.x);
        float o1 = fmaxf(0.f, (v[i].y - mu) * rs * gv.y + bv.y);
        float o2 = fmaxf(0.f, (v[i].z - mu) * rs * gv.z + bv.z);
        float o3 = fmaxf(0.f, (v[i].w - mu) * rs * gv.w + bv.w);
        __nv_bfloat162 p0 = __floats2bfloat162_rn(o0, o1);
        __nv_bfloat162 p1 = __floats2bfloat162_rn(o2, o3);
        uint2 u; u.x = *(uint32_t*)&p0; u.y = *(uint32_t*)&p1;
        *(uint2*)(op + c) = u;
    }
}

// ---------------------------------------------------------------------------
// Warp-per-row LayerNorm + ReLU + linear(384->1) + exp.
// ---------------------------------------------------------------------------
__global__ __launch_bounds__(256)
void ln_linear_exp(const float* __restrict__ in, const float* __restrict__ g,
                   const float* __restrict__ beta, const float* __restrict__ wl,
                   const float* __restrict__ bl, float* __restrict__ pred)
{
    const int row  = (blockIdx.x * 256 + threadIdx.x) >> 5;
    const int lane = threadIdx.x & 31;
    const float4* p = (const float4*)(in + (size_t)row * HH);

    float4 v[3];
    float s = 0.f, sq = 0.f;
#pragma unroll
    for (int i = 0; i < 3; i++) {
        v[i] = p[lane + 32 * i];
        s  += v[i].x + v[i].y + v[i].z + v[i].w;
        sq += v[i].x * v[i].x + v[i].y * v[i].y + v[i].z * v[i].z + v[i].w * v[i].w;
    }
#pragma unroll
    for (int off = 16; off > 0; off >>= 1) {
        s  += __shfl_xor_sync(0xffffffffu, s,  off);
        sq += __shfl_xor_sync(0xffffffffu, sq, off);
    }
    const float mu = s * (1.f / HH);
    const float rs = rsqrtf(sq * (1.f / HH) - mu * mu + 1e-5f);

    float d = 0.f;
#pragma unroll
    for (int i = 0; i < 3; i++) {
        const int c = (lane + 32 * i) * 4;
        const float4 gv = *(const float4*)(g + c);
        const float4 bv = *(const float4*)(beta + c);
        const float4 wv = *(const float4*)(wl + c);
        d += fmaxf(0.f, (v[i].x - mu) * rs * gv.x + bv.x) * wv.x;
        d += fmaxf(0.f, (v[i].y - mu) * rs * gv.y + bv.y) * wv.y;
        d += fmaxf(0.f, (v[i].z - mu) * rs * gv.z + bv.z) * wv.z;
        d += fmaxf(0.f, (v[i].w - mu) * rs * gv.w + bv.w) * wv.w;
    }
#pragma unroll
    for (int off = 16; off > 0; off >>= 1)
        d += __shfl_xor_sync(0xffffffffu, d, off);
    if (lane == 0) pred[row] = expf(d + bl[0]);
}

// ---------------------------------------------------------------------------
__global__ __launch_bounds__(256)
void f32_to_bf16(const float* __restrict__ x, __nv_bfloat16* __restrict__ y)
{
    const size_t i = ((size_t)blockIdx.x * 256 + threadIdx.x) * 4;
    float4 v = *(const float4*)(x + i);
    __nv_bfloat162 p0 = __floats2bfloat162_rn(v.x, v.y);
    __nv_bfloat162 p1 = __floats2bfloat162_rn(v.z, v.w);
    uint2 o;
    o.x = *(uint32_t*)&p0; o.y = *(uint32_t*)&p1;
    *(uint2*)(y + i) = o;
}

// Wt[n][kc] = W[kc][n], fp32 -> bf16. blockIdx.y selects weight set.
__global__ __launch_bounds__(256)
void wtrans2(const float* __restrict__ w1, __nv_bfloat16* __restrict__ wt1,
             const float* __restrict__ w2, __nv_bfloat16* __restrict__ wt2)
{
    const int id = blockIdx.x * 256 + threadIdx.x;   // HH*KDIM = 442368 exact
    const int n  = id / KDIM;
    const int kc = id - n * KDIM;
    if (blockIdx.y == 0) wt1[id] = __float2bfloat16(w1[(size_t)kc * HH + n]);
    else                 wt2[id] = __float2bfloat16(w2[(size_t)kc * HH + n]);
}

// ---------------------------------------------------------------------------
__global__ __launch_bounds__(1024)
void cumsum_kernel(const int* __restrict__ dur, int* __restrict__ cum)
{
    __shared__ int buf[SS];
    const int b = blockIdx.x, tid = threadIdx.x;
    buf[tid] = dur[b * SS + tid];
    __syncthreads();
#pragma unroll
    for (int off = 1; off < SS; off <<= 1) {
        int t = buf[tid];
        int u = (tid >= off) ? buf[tid - off] : 0;
        __syncthreads();
        buf[tid] = t + u;
        __syncthreads();
    }
    cum[b * SS + tid] = buf[tid];
}

__global__ __launch_bounds__(256)
void gather_kernel(const float* __restrict__ x, const int* __restrict__ cum,
                   float* __restrict__ out)
{
    const int gw   = (blockIdx.x * 256 + threadIdx.x) >> 5;
    const int lane = threadIdx.x & 31;
    const int b = gw / MAX_OUT_T;
    const int t = gw - b * MAX_OUT_T;

    const int* c = cum + b * SS;
    const bool valid = t < c[SS - 1];
    int lo = 0, hi = SS;
    while (lo < hi) {
        int mid = (lo + hi) >> 1;
        if (c[mid] <= t) lo = mid + 1; else hi = mid;
    }
    const int src = min(lo, SS - 1);

    const float4* xin = (const float4*)(x + ((size_t)b * SS + src) * CC);
    float4* o = (float4*)(out + (size_t)gw * CC);
    const float4 z = make_float4(0.f, 0.f, 0.f, 0.f);
#pragma unroll
    for (int i = 0; i < 3; i++)
        o[lane + i * 32] = valid ? xin[lane + i * 32] : z;
}

// ---------------------------------------------------------------------------
extern "C" void kernel_launch(void* const* d_in, const int* in_sizes, int n_in,
                              void* d_out, int out_size)
{
    const float* x     = (const float*)d_in[0];
    const int*   dur   = (const int*)  d_in[1];
    const float* w1    = (const float*)d_in[2];
    const float* b1    = (const float*)d_in[3];
    const float* g1    = (const float*)d_in[4];
    const float* beta1 = (const float*)d_in[5];
    const float* w2    = (const float*)d_in[6];
    const float* b2    = (const float*)d_in[7];
    const float* g2    = (const float*)d_in[8];
    const float* beta2 = (const float*)d_in[9];
    const float* wl    = (const float*)d_in[10];
    const float* bl    = (const float*)d_in[11];
    float* out = (float*)d_out;

    __nv_bfloat16 *xb, *h1b, *wt1, *wt2;
    float *tmp1, *tmp2; int* cum;
    cudaGetSymbolAddress((void**)&xb,   g_xb);
    cudaGetSymbolAddress((void**)&h1b,  g_h1b);
    cudaGetSymbolAddress((void**)&wt1,  g_wt1);
    cudaGetSymbolAddress((void**)&wt2,  g_wt2);
    cudaGetSymbolAddress((void**)&tmp1, g_tmp1);
    cudaGetSymbolAddress((void**)&tmp2, g_tmp2);
    cudaGetSymbolAddress((void**)&cum,  g_cum);

    cudaFuncSetAttribute(conv_gemm_mma, cudaFuncAttributeMaxDynamicSharedMemorySize, GEMM_SMEM);

    static cudaStream_t s2 = nullptr;
    static cudaEvent_t  ev_fork = nullptr, ev_wt = nullptr, ev_join = nullptr;
    if (s2 == nullptr) {
        cudaStreamCreateWithFlags(&s2, cudaStreamNonBlocking);
        cudaEventCreateWithFlags(&ev_fork, cudaEventDisableTiming);
        cudaEventCreateWithFlags(&ev_wt,   cudaEventDisableTiming);
        cudaEventCreateWithFlags(&ev_join, cudaEventDisableTiming);
    }

    // ---- fork: weight transpose + length regulation on s2 ------------------
    cudaEventRecord(ev_fork, (cudaStream_t)0);
    cudaStreamWaitEvent(s2, ev_fork, 0);
    {
        dim3 wg((HH * KDIM) / 256, 2);
        wtrans2<<<wg, 256, 0, s2>>>(w1, wt1, w2, wt2);
    }
    cudaEventRecord(ev_wt, s2);                       // wt1/wt2 ready marker
    cumsum_kernel<<<BB, SS, 0, s2>>>(dur, cum);
    gather_kernel<<<(BB * MAX_OUT_T) / 8, 256, 0, s2>>>(x, cum, out);
    cudaEventRecord(ev_join, s2);

    // ---- predictor chain on the main stream --------------------------------
    f32_to_bf16<<<(M_TOTAL * CC) / 1024, 256>>>(x, xb);
    cudaStreamWaitEvent((cudaStream_t)0, ev_wt, 0);   // need wt1 before GEMM1

    dim3 gemm_grid(HH / 128, M_TOTAL / 128);   // (3, 256)
    conv_gemm_mma<<<gemm_grid, 256, GEMM_SMEM>>>(xb, wt1, b1, tmp1);
    ln_relu_bf16<<<M_TOTAL / 8, 256>>>(tmp1, g1, beta1, h1b);
    conv_gemm_mma<<<gemm_grid, 256, GEMM_SMEM>>>(h1b, wt2, b2, tmp2);
    ln_linear_exp<<<M_TOTAL / 8, 256>>>(tmp2, g2, beta2, wl, bl, out + PRED_OFFSET);

    // ---- join ---------------------------------------------------------------
    cudaStreamWaitEvent((cudaStream_t)0, ev_join, 0);
}

// round 8
// speedup vs baseline: 1.0530x; 1.0530x over previous
#include <cuda_runtime.h>
#include <cuda_bf16.h>
#include <math.h>
#include <stdint.h>

#define BB 32
#define SS 1024
#define CC 384
#define HH 384
#define MAX_OUT_T 3072
#define M_TOTAL (BB*SS)          // 32768
#define KDIM (3*CC)              // 1152
#define PRED_OFFSET ((size_t)BB*MAX_OUT_T*CC)

// ---------------- scratch (static device globals: allocation-free) ----------
__device__ __nv_bfloat16 g_xb [(size_t)M_TOTAL*CC];
__device__ __nv_bfloat16 g_h1b[(size_t)M_TOTAL*HH];
__device__ __nv_bfloat16 g_wt1[(size_t)HH*KDIM];
__device__ __nv_bfloat16 g_wt2[(size_t)HH*KDIM];
__device__ float g_tmp1[(size_t)M_TOTAL*HH];
__device__ float g_tmp2[(size_t)M_TOTAL*HH];
__device__ int   g_cum[BB*SS];

// ---------------- PTX helpers (baseline PTX only) ----------------------------
__device__ __forceinline__ uint32_t smem_u32(const void* p) {
    uint32_t a;
    asm("{ .reg .u64 t; cvta.to.shared.u64 t, %1; cvt.u32.u64 %0, t; }" : "=r"(a) : "l"(p));
    return a;
}
__device__ __forceinline__ void cp_async16(uint32_t saddr, const void* gptr, uint32_t sz) {
    asm volatile("cp.async.cg.shared.global [%0], [%1], 16, %2;"
                 :: "r"(saddr), "l"(gptr), "r"(sz) : "memory");
}
__device__ __forceinline__ void cp_commit() {
    asm volatile("cp.async.commit_group;" ::: "memory");
}
template <int N>
__device__ __forceinline__ void cp_wait() {
    asm volatile("cp.async.wait_group %0;" :: "n"(N) : "memory");
}
__device__ __forceinline__ void ldmatrix_x4(uint32_t& r0, uint32_t& r1, uint32_t& r2,
                                            uint32_t& r3, uint32_t addr) {
    asm volatile("ldmatrix.sync.aligned.m8n8.x4.shared.b16 {%0,%1,%2,%3}, [%4];"
                 : "=r"(r0), "=r"(r1), "=r"(r2), "=r"(r3) : "r"(addr));
}
__device__ __forceinline__ void mma_16816(float& d0, float& d1, float& d2, float& d3,
                                          uint32_t a0, uint32_t a1, uint32_t a2, uint32_t a3,
                                          uint32_t b0, uint32_t b1) {
    asm volatile("mma.sync.aligned.m16n8k16.row.col.f32.bf16.bf16.f32 "
                 "{%0,%1,%2,%3}, {%4,%5,%6,%7}, {%8,%9}, {%0,%1,%2,%3};"
                 : "+f"(d0), "+f"(d1), "+f"(d2), "+f"(d3)
                 : "r"(a0), "r"(a1), "r"(a2), "r"(a3), "r"(b0), "r"(b1));
}

// ---------------------------------------------------------------------------
// Conv-as-GEMM on tensor cores (mma.sync bf16), 3-stage cp.async pipeline.
// (round-6 mainloop: prefetch issued immediately after the barrier)
// ---------------------------------------------------------------------------
#define NSTEPS 18
#define TILE_B 16384                       // 128 rows x 128 bytes
#define GEMM_SMEM (6*TILE_B)               // 3 stages x (A,B)

__global__ __launch_bounds__(256, 2)
void conv_gemm_mma(const __nv_bfloat16* __restrict__ A,
                   const __nv_bfloat16* __restrict__ Wt,
                   const float* __restrict__ bias,
                   float* __restrict__ out)
{
    extern __shared__ __align__(1024) char smem[];
    const uint32_t sbase = smem_u32(smem);
    const int tid  = threadIdx.x;
    const int wid  = tid >> 5;
    const int lane = tid & 31;
    const int warp_m = wid & 1;
    const int warp_n = wid >> 1;
    const int n0 = blockIdx.x * 128;
    const int m0 = blockIdx.y * 128;

    const int lrow = tid >> 3;              // 0..31 (+32*i)
    const int lcx  = (tid & 7) * 16;

    auto load_tiles = [&](int step, int stage) {
        const uint32_t abase = sbase + (uint32_t)stage * 2 * TILE_B;
        const uint32_t bbase = abase + TILE_B;
        const int k  = step / 6;
        const int c0 = (step - k * 6) * 64;
#pragma unroll
        for (int i = 0; i < 4; i++) {
            const int row = lrow + 32 * i;
            uint32_t off = (uint32_t)(row * 128 + lcx);
            uint32_t sw  = off ^ ((off >> 3) & 0x70);
            const int gm  = m0 + row;
            const int ss  = (gm & (SS - 1)) + k - 1;
            const bool valid = (ss >= 0) && (ss < SS);
            const char* gpa = (const char*)A + ((size_t)(gm + k - 1) * CC + c0) * 2 + lcx;
            if (!valid) gpa = (const char*)A;
            cp_async16(abase + sw, gpa, valid ? 16u : 0u);
            const char* gpb = (const char*)Wt + ((size_t)(n0 + row) * KDIM + step * 64) * 2 + lcx;
            cp_async16(bbase + sw, gpb, 16u);
        }
    };

    float acc[4][4][4];
#pragma unroll
    for (int i = 0; i < 4; i++)
#pragma unroll
        for (int j = 0; j < 4; j++)
#pragma unroll
            for (int q = 0; q < 4; q++) acc[i][j][q] = 0.f;

    const int fr_row = ((lane >> 3) & 1) * 8 + (lane & 7);
    const int fr_kb  = (lane >> 4) * 16;
    const uint32_t cxor = (uint32_t)((fr_row & 7) << 4);
    const uint32_t a_row_base = (uint32_t)((warp_m * 64 + fr_row) * 128);
    const uint32_t b_row_base = (uint32_t)((warp_n * 32 + fr_row) * 128);

    load_tiles(0, 0); cp_commit();
    load_tiles(1, 1); cp_commit();

    int stage = 0;
    for (int step = 0; step < NSTEPS; ++step) {
        cp_wait<1>();
        __syncthreads();

        // prefetch step+2 into the stage we just vacated (round-6 placement)
        {
            const int pf = stage + 2 - ((stage + 2 >= 3) ? 3 : 0);
            if (step + 2 < NSTEPS) load_tiles(step + 2, pf);
            cp_commit();
        }

        const uint32_t sa = sbase + (uint32_t)stage * 2 * TILE_B;
        const uint32_t sb = sa + TILE_B;

        uint32_t ball[4][2][4];
#pragma unroll
        for (int ks = 0; ks < 4; ks++) {
            const uint32_t col = ((uint32_t)(ks * 32 + fr_kb)) ^ cxor;
#pragma unroll
            for (int nt = 0; nt < 2; nt++) {
                const uint32_t addr = sb + b_row_base + (uint32_t)(nt * 2048) + col;
                ldmatrix_x4(ball[ks][nt][0], ball[ks][nt][1], ball[ks][nt][2], ball[ks][nt][3], addr);
            }
        }

#pragma unroll
        for (int ks = 0; ks < 4; ks++) {
            const uint32_t col = ((uint32_t)(ks * 32 + fr_kb)) ^ cxor;
            uint32_t a[4][4];
#pragma unroll
            for (int mt = 0; mt < 4; mt++) {
                const uint32_t addr = sa + a_row_base + (uint32_t)(mt * 2048) + col;
                ldmatrix_x4(a[mt][0], a[mt][1], a[mt][2], a[mt][3], addr);
            }
#pragma unroll
            for (int mt = 0; mt < 4; mt++)
#pragma unroll
                for (int nt = 0; nt < 2; nt++)
#pragma unroll
                    for (int h = 0; h < 2; h++) {
                        const int j = nt * 2 + h;
                        mma_16816(acc[mt][j][0], acc[mt][j][1], acc[mt][j][2], acc[mt][j][3],
                                  a[mt][0], a[mt][1], a[mt][2], a[mt][3],
                                  ball[ks][nt][h], ball[ks][nt][2 + h]);
                    }
        }
        stage = (stage == 2) ? 0 : stage + 1;
    }

    const int g = lane >> 2;
    const int t = lane & 3;
#pragma unroll
    for (int mt = 0; mt < 4; mt++) {
        const int row0 = m0 + warp_m * 64 + mt * 16 + g;
#pragma unroll
        for (int j = 0; j < 4; j++) {
            const int col = n0 + warp_n * 32 + j * 8 + t * 2;
            const float2 bv = *(const float2*)(bias + col);
            float2 o0 = make_float2(acc[mt][j][0] + bv.x, acc[mt][j][1] + bv.y);
            float2 o1 = make_float2(acc[mt][j][2] + bv.x, acc[mt][j][3] + bv.y);
            *(float2*)(out + (size_t)row0 * HH + col)       = o0;
            *(float2*)(out + (size_t)(row0 + 8) * HH + col) = o1;
        }
    }
}

// ---------------------------------------------------------------------------
// Warp-per-row LayerNorm + ReLU -> bf16.
// ---------------------------------------------------------------------------
__global__ __launch_bounds__(256)
void ln_relu_bf16(const float* __restrict__ in, const float* __restrict__ g,
                  const float* __restrict__ beta, __nv_bfloat16* __restrict__ outb)
{
    const int row  = (blockIdx.x * 256 + threadIdx.x) >> 5;
    const int lane = threadIdx.x & 31;
    const float4* p = (const float4*)(in + (size_t)row * HH);

    float4 v[3];
    float s = 0.f, sq = 0.f;
#pragma unroll
    for (int i = 0; i < 3; i++) {
        v[i] = p[lane + 32 * i];
        s  += v[i].x + v[i].y + v[i].z + v[i].w;
        sq += v[i].x * v[i].x + v[i].y * v[i].y + v[i].z * v[i].z + v[i].w * v[i].w;
    }
#pragma unroll
    for (int off = 16; off > 0; off >>= 1) {
        s  += __shfl_xor_sync(0xffffffffu, s,  off);
        sq += __shfl_xor_sync(0xffffffffu, sq, off);
    }
    const float mu = s * (1.f / HH);
    const float rs = rsqrtf(sq * (1.f / HH) - mu * mu + 1e-5f);

    __nv_bfloat16* op = outb + (size_t)row * HH;
#pragma unroll
    for (int i = 0; i < 3; i++) {
        const int c = (lane + 32 * i) * 4;
        const float4 gv = *(const float4*)(g + c);
        const float4 bv = *(const float4*)(beta + c);
        float o0 = fmaxf(0.f, (v[i].x - mu) * rs * gv.x + bv.x);
        float o1 = fmaxf(0.f, (v[i].y - mu) * rs * gv.y + bv.y);
        float o2 = fmaxf(0.f, (v[i].z - mu) * rs * gv.z + bv.z);
        float o3 = fmaxf(0.f, (v[i].w - mu) * rs * gv.w + bv.w);
        __nv_bfloat162 p0 = __floats2bfloat162_rn(o0, o1);
        __nv_bfloat162 p1 = __floats2bfloat162_rn(o2, o3);
        uint2 u; u.x = *(uint32_t*)&p0; u.y = *(uint32_t*)&p1;
        *(uint2*)(op + c) = u;
    }
}

// ---------------------------------------------------------------------------
// Warp-per-row LayerNorm + ReLU + linear(384->1) + exp.
// ---------------------------------------------------------------------------
__global__ __launch_bounds__(256)
void ln_linear_exp(const float* __restrict__ in, const float* __restrict__ g,
                   const float* __restrict__ beta, const float* __restrict__ wl,
                   const float* __restrict__ bl, float* __restrict__ pred)
{
    const int row  = (blockIdx.x * 256 + threadIdx.x) >> 5;
    const int lane = threadIdx.x & 31;
    const float4* p = (const float4*)(in + (size_t)row * HH);

    float4 v[3];
    float s = 0.f, sq = 0.f;
#pragma unroll
    for (int i = 0; i < 3; i++) {
        v[i] = p[lane + 32 * i];
        s  += v[i].x + v[i].y + v[i].z + v[i].w;
        sq += v[i].x * v[i].x + v[i].y * v[i].y + v[i].z * v[i].z + v[i].w * v[i].w;
    }
#pragma unroll
    for (int off = 16; off > 0; off >>= 1) {
        s  += __shfl_xor_sync(0xffffffffu, s,  off);
        sq += __shfl_xor_sync(0xffffffffu, sq, off);
    }
    const float mu = s * (1.f / HH);
    const float rs = rsqrtf(sq * (1.f / HH) - mu * mu + 1e-5f);

    float d = 0.f;
#pragma unroll
    for (int i = 0; i < 3; i++) {
        const int c = (lane + 32 * i) * 4;
        const float4 gv = *(const float4*)(g + c);
        const float4 bv = *(const float4*)(beta + c);
        const float4 wv = *(const float4*)(wl + c);
        d += fmaxf(0.f, (v[i].x - mu) * rs * gv.x + bv.x) * wv.x;
        d += fmaxf(0.f, (v[i].y - mu) * rs * gv.y + bv.y) * wv.y;
        d += fmaxf(0.f, (v[i].z - mu) * rs * gv.z + bv.z) * wv.z;
        d += fmaxf(0.f, (v[i].w - mu) * rs * gv.w + bv.w) * wv.w;
    }
#pragma unroll
    for (int off = 16; off > 0; off >>= 1)
        d += __shfl_xor_sync(0xffffffffu, d, off);
    if (lane == 0) pred[row] = expf(d + bl[0]);
}

// ---------------------------------------------------------------------------
__global__ __launch_bounds__(256)
void f32_to_bf16(const float* __restrict__ x, __nv_bfloat16* __restrict__ y)
{
    const size_t i = ((size_t)blockIdx.x * 256 + threadIdx.x) * 4;
    float4 v = *(const float4*)(x + i);
    __nv_bfloat162 p0 = __floats2bfloat162_rn(v.x, v.y);
    __nv_bfloat162 p1 = __floats2bfloat162_rn(v.z, v.w);
    uint2 o;
    o.x = *(uint32_t*)&p0; o.y = *(uint32_t*)&p1;
    *(uint2*)(y + i) = o;
}

// Wt[n][kc] = W[kc][n], fp32 -> bf16. blockIdx.y selects weight set.
__global__ __launch_bounds__(256)
void wtrans2(const float* __restrict__ w1, __nv_bfloat16* __restrict__ wt1,
             const float* __restrict__ w2, __nv_bfloat16* __restrict__ wt2)
{
    const int id = blockIdx.x * 256 + threadIdx.x;   // HH*KDIM = 442368 exact
    const int n  = id / KDIM;
    const int kc = id - n * KDIM;
    if (blockIdx.y == 0) wt1[id] = __float2bfloat16(w1[(size_t)kc * HH + n]);
    else                 wt2[id] = __float2bfloat16(w2[(size_t)kc * HH + n]);
}

// ---------------------------------------------------------------------------
__global__ __launch_bounds__(1024)
void cumsum_kernel(const int* __restrict__ dur, int* __restrict__ cum)
{
    __shared__ int buf[SS];
    const int b = blockIdx.x, tid = threadIdx.x;
    buf[tid] = dur[b * SS + tid];
    __syncthreads();
#pragma unroll
    for (int off = 1; off < SS; off <<= 1) {
        int t = buf[tid];
        int u = (tid >= off) ? buf[tid - off] : 0;
        __syncthreads();
        buf[tid] = t + u;
        __syncthreads();
    }
    cum[b * SS + tid] = buf[tid];
}

__global__ __launch_bounds__(256)
void gather_kernel(const float* __restrict__ x, const int* __restrict__ cum,
                   float* __restrict__ out)
{
    const int gw   = (blockIdx.x * 256 + threadIdx.x) >> 5;
    const int lane = threadIdx.x & 31;
    const int b = gw / MAX_OUT_T;
    const int t = gw - b * MAX_OUT_T;

    const int* c = cum + b * SS;
    const bool valid = t < c[SS - 1];
    int lo = 0, hi = SS;
    while (lo < hi) {
        int mid = (lo + hi) >> 1;
        if (c[mid] <= t) lo = mid + 1; else hi = mid;
    }
    const int src = min(lo, SS - 1);

    const float4* xin = (const float4*)(x + ((size_t)b * SS + src) * CC);
    float4* o = (float4*)(out + (size_t)gw * CC);
    const float4 z = make_float4(0.f, 0.f, 0.f, 0.f);
#pragma unroll
    for (int i = 0; i < 3; i++)
        o[lane + i * 32] = valid ? xin[lane + i * 32] : z;
}

// ---------------------------------------------------------------------------
extern "C" void kernel_launch(void* const* d_in, const int* in_sizes, int n_in,
                              void* d_out, int out_size)
{
    const float* x     = (const float*)d_in[0];
    const int*   dur   = (const int*)  d_in[1];
    const float* w1    = (const float*)d_in[2];
    const float* b1    = (const float*)d_in[3];
    const float* g1    = (const float*)d_in[4];
    const float* beta1 = (const float*)d_in[5];
    const float* w2    = (const float*)d_in[6];
    const float* b2    = (const float*)d_in[7];
    const float* g2    = (const float*)d_in[8];
    const float* beta2 = (const float*)d_in[9];
    const float* wl    = (const float*)d_in[10];
    const float* bl    = (const float*)d_in[11];
    float* out = (float*)d_out;

    __nv_bfloat16 *xb, *h1b, *wt1, *wt2;
    float *tmp1, *tmp2; int* cum;
    cudaGetSymbolAddress((void**)&xb,   g_xb);
    cudaGetSymbolAddress((void**)&h1b,  g_h1b);
    cudaGetSymbolAddress((void**)&wt1,  g_wt1);
    cudaGetSymbolAddress((void**)&wt2,  g_wt2);
    cudaGetSymbolAddress((void**)&tmp1, g_tmp1);
    cudaGetSymbolAddress((void**)&tmp2, g_tmp2);
    cudaGetSymbolAddress((void**)&cum,  g_cum);

    cudaFuncSetAttribute(conv_gemm_mma, cudaFuncAttributeMaxDynamicSharedMemorySize, GEMM_SMEM);

    static cudaStream_t s2 = nullptr;
    static cudaEvent_t  ev_fork = nullptr, ev_wt = nullptr, ev_join = nullptr;
    if (s2 == nullptr) {
        cudaStreamCreateWithFlags(&s2, cudaStreamNonBlocking);
        cudaEventCreateWithFlags(&ev_fork, cudaEventDisableTiming);
        cudaEventCreateWithFlags(&ev_wt,   cudaEventDisableTiming);
        cudaEventCreateWithFlags(&ev_join, cudaEventDisableTiming);
    }

    // ---- fork: weight transpose + length regulation on s2 ------------------
    cudaEventRecord(ev_fork, (cudaStream_t)0);
    cudaStreamWaitEvent(s2, ev_fork, 0);
    {
        dim3 wg((HH * KDIM) / 256, 2);
        wtrans2<<<wg, 256, 0, s2>>>(w1, wt1, w2, wt2);
    }
    cudaEventRecord(ev_wt, s2);                       // wt1/wt2 ready marker
    cumsum_kernel<<<BB, SS, 0, s2>>>(dur, cum);
    gather_kernel<<<(BB * MAX_OUT_T) / 8, 256, 0, s2>>>(x, cum, out);
    cudaEventRecord(ev_join, s2);

    // ---- predictor chain on the main stream --------------------------------
    f32_to_bf16<<<(M_TOTAL * CC) / 1024, 256>>>(x, xb);
    cudaStreamWaitEvent((cudaStream_t)0, ev_wt, 0);   // need wt1 before GEMM1

    dim3 gemm_grid(HH / 128, M_TOTAL / 128);   // (3, 256)
    conv_gemm_mma<<<gemm_grid, 256, GEMM_SMEM>>>(xb, wt1, b1, tmp1);
    ln_relu_bf16<<<M_TOTAL / 8, 256>>>(tmp1, g1, beta1, h1b);
    conv_gemm_mma<<<gemm_grid, 256, GEMM_SMEM>>>(h1b, wt2, b2, tmp2);
    ln_linear_exp<<<M_TOTAL / 8, 256>>>(tmp2, g2, beta2, wl, bl, out + PRED_OFFSET);

    // ---- join ---------------------------------------------------------------
    cudaStreamWaitEvent((cudaStream_t)0, ev_join, 0);
}

// round 9
// speedup vs baseline: 1.0569x; 1.0037x over previous
#include <cuda_runtime.h>
#include <cuda_bf16.h>
#include <math.h>
#include <stdint.h>

#define BB 32
#define SS 1024
#define CC 384
#define HH 384
#define MAX_OUT_T 3072
#define M_TOTAL (BB*SS)          // 32768
#define KDIM (3*CC)              // 1152
#define PRED_OFFSET ((size_t)BB*MAX_OUT_T*CC)

// ---------------- scratch (static device globals: allocation-free) ----------
__device__ __nv_bfloat16 g_xb  [(size_t)M_TOTAL*CC];
__device__ __nv_bfloat16 g_h1b [(size_t)M_TOTAL*HH];
__device__ __nv_bfloat16 g_wt1 [(size_t)HH*KDIM];
__device__ __nv_bfloat16 g_wt2 [(size_t)HH*KDIM];
__device__ __nv_bfloat16 g_t1b [(size_t)M_TOTAL*HH];   // GEMM1 out (bf16)
__device__ __nv_bfloat16 g_t2b [(size_t)M_TOTAL*HH];   // GEMM2 out (bf16)
__device__ int   g_cum[BB*SS];

// ---------------- PTX helpers (baseline PTX only) ----------------------------
__device__ __forceinline__ uint32_t smem_u32(const void* p) {
    uint32_t a;
    asm("{ .reg .u64 t; cvta.to.shared.u64 t, %1; cvt.u32.u64 %0, t; }" : "=r"(a) : "l"(p));
    return a;
}
__device__ __forceinline__ void cp_async16(uint32_t saddr, const void* gptr, uint32_t sz) {
    asm volatile("cp.async.cg.shared.global [%0], [%1], 16, %2;"
                 :: "r"(saddr), "l"(gptr), "r"(sz) : "memory");
}
__device__ __forceinline__ void cp_commit() {
    asm volatile("cp.async.commit_group;" ::: "memory");
}
template <int N>
__device__ __forceinline__ void cp_wait() {
    asm volatile("cp.async.wait_group %0;" :: "n"(N) : "memory");
}
__device__ __forceinline__ void ldmatrix_x4(uint32_t& r0, uint32_t& r1, uint32_t& r2,
                                            uint32_t& r3, uint32_t addr) {
    asm volatile("ldmatrix.sync.aligned.m8n8.x4.shared.b16 {%0,%1,%2,%3}, [%4];"
                 : "=r"(r0), "=r"(r1), "=r"(r2), "=r"(r3) : "r"(addr));
}
__device__ __forceinline__ void mma_16816(float& d0, float& d1, float& d2, float& d3,
                                          uint32_t a0, uint32_t a1, uint32_t a2, uint32_t a3,
                                          uint32_t b0, uint32_t b1) {
    asm volatile("mma.sync.aligned.m16n8k16.row.col.f32.bf16.bf16.f32 "
                 "{%0,%1,%2,%3}, {%4,%5,%6,%7}, {%8,%9}, {%0,%1,%2,%3};"
                 : "+f"(d0), "+f"(d1), "+f"(d2), "+f"(d3)
                 : "r"(a0), "r"(a1), "r"(a2), "r"(a3), "r"(b0), "r"(b1));
}

// ---------------------------------------------------------------------------
// Conv-as-GEMM on tensor cores (mma.sync bf16), 3-stage cp.async pipeline.
// (round-6 mainloop; epilogue now emits bf16)
// ---------------------------------------------------------------------------
#define NSTEPS 18
#define TILE_B 16384                       // 128 rows x 128 bytes
#define GEMM_SMEM (6*TILE_B)               // 3 stages x (A,B)

__global__ __launch_bounds__(256, 2)
void conv_gemm_mma(const __nv_bfloat16* __restrict__ A,
                   const __nv_bfloat16* __restrict__ Wt,
                   const float* __restrict__ bias,
                   __nv_bfloat16* __restrict__ out)
{
    extern __shared__ __align__(1024) char smem[];
    const uint32_t sbase = smem_u32(smem);
    const int tid  = threadIdx.x;
    const int wid  = tid >> 5;
    const int lane = tid & 31;
    const int warp_m = wid & 1;
    const int warp_n = wid >> 1;
    const int n0 = blockIdx.x * 128;
    const int m0 = blockIdx.y * 128;

    const int lrow = tid >> 3;              // 0..31 (+32*i)
    const int lcx  = (tid & 7) * 16;

    auto load_tiles = [&](int step, int stage) {
        const uint32_t abase = sbase + (uint32_t)stage * 2 * TILE_B;
        const uint32_t bbase = abase + TILE_B;
        const int k  = step / 6;
        const int c0 = (step - k * 6) * 64;
#pragma unroll
        for (int i = 0; i < 4; i++) {
            const int row = lrow + 32 * i;
            uint32_t off = (uint32_t)(row * 128 + lcx);
            uint32_t sw  = off ^ ((off >> 3) & 0x70);
            const int gm  = m0 + row;
            const int ss  = (gm & (SS - 1)) + k - 1;
            const bool valid = (ss >= 0) && (ss < SS);
            const char* gpa = (const char*)A + ((size_t)(gm + k - 1) * CC + c0) * 2 + lcx;
            if (!valid) gpa = (const char*)A;
            cp_async16(abase + sw, gpa, valid ? 16u : 0u);
            const char* gpb = (const char*)Wt + ((size_t)(n0 + row) * KDIM + step * 64) * 2 + lcx;
            cp_async16(bbase + sw, gpb, 16u);
        }
    };

    float acc[4][4][4];
#pragma unroll
    for (int i = 0; i < 4; i++)
#pragma unroll
        for (int j = 0; j < 4; j++)
#pragma unroll
            for (int q = 0; q < 4; q++) acc[i][j][q] = 0.f;

    const int fr_row = ((lane >> 3) & 1) * 8 + (lane & 7);
    const int fr_kb  = (lane >> 4) * 16;
    const uint32_t cxor = (uint32_t)((fr_row & 7) << 4);
    const uint32_t a_row_base = (uint32_t)((warp_m * 64 + fr_row) * 128);
    const uint32_t b_row_base = (uint32_t)((warp_n * 32 + fr_row) * 128);

    load_tiles(0, 0); cp_commit();
    load_tiles(1, 1); cp_commit();

    int stage = 0;
    for (int step = 0; step < NSTEPS; ++step) {
        cp_wait<1>();
        __syncthreads();

        {
            const int pf = stage + 2 - ((stage + 2 >= 3) ? 3 : 0);
            if (step + 2 < NSTEPS) load_tiles(step + 2, pf);
            cp_commit();
        }

        const uint32_t sa = sbase + (uint32_t)stage * 2 * TILE_B;
        const uint32_t sb = sa + TILE_B;

        uint32_t ball[4][2][4];
#pragma unroll
        for (int ks = 0; ks < 4; ks++) {
            const uint32_t col = ((uint32_t)(ks * 32 + fr_kb)) ^ cxor;
#pragma unroll
            for (int nt = 0; nt < 2; nt++) {
                const uint32_t addr = sb + b_row_base + (uint32_t)(nt * 2048) + col;
                ldmatrix_x4(ball[ks][nt][0], ball[ks][nt][1], ball[ks][nt][2], ball[ks][nt][3], addr);
            }
        }

#pragma unroll
        for (int ks = 0; ks < 4; ks++) {
            const uint32_t col = ((uint32_t)(ks * 32 + fr_kb)) ^ cxor;
            uint32_t a[4][4];
#pragma unroll
            for (int mt = 0; mt < 4; mt++) {
                const uint32_t addr = sa + a_row_base + (uint32_t)(mt * 2048) + col;
                ldmatrix_x4(a[mt][0], a[mt][1], a[mt][2], a[mt][3], addr);
            }
#pragma unroll
            for (int mt = 0; mt < 4; mt++)
#pragma unroll
                for (int nt = 0; nt < 2; nt++)
#pragma unroll
                    for (int h = 0; h < 2; h++) {
                        const int j = nt * 2 + h;
                        mma_16816(acc[mt][j][0], acc[mt][j][1], acc[mt][j][2], acc[mt][j][3],
                                  a[mt][0], a[mt][1], a[mt][2], a[mt][3],
                                  ball[ks][nt][h], ball[ks][nt][2 + h]);
                    }
        }
        stage = (stage == 2) ? 0 : stage + 1;
    }

    // ---- epilogue: bias add, bf16 stores ------------------------------------
    const int g = lane >> 2;
    const int t = lane & 3;
#pragma unroll
    for (int mt = 0; mt < 4; mt++) {
        const int row0 = m0 + warp_m * 64 + mt * 16 + g;
#pragma unroll
        for (int j = 0; j < 4; j++) {
            const int col = n0 + warp_n * 32 + j * 8 + t * 2;
            const float2 bv = *(const float2*)(bias + col);
            __nv_bfloat162 o0 = __floats2bfloat162_rn(acc[mt][j][0] + bv.x, acc[mt][j][1] + bv.y);
            __nv_bfloat162 o1 = __floats2bfloat162_rn(acc[mt][j][2] + bv.x, acc[mt][j][3] + bv.y);
            *(__nv_bfloat162*)(out + (size_t)row0 * HH + col)       = o0;
            *(__nv_bfloat162*)(out + (size_t)(row0 + 8) * HH + col) = o1;
        }
    }
}

// ---------------------------------------------------------------------------
// Warp-per-row LayerNorm + ReLU, bf16 in -> bf16 out. fp32 math.
// ---------------------------------------------------------------------------
__global__ __launch_bounds__(256)
void ln_relu_bf16(const __nv_bfloat16* __restrict__ in, const float* __restrict__ g,
                  const float* __restrict__ beta, __nv_bfloat16* __restrict__ outb)
{
    const int row  = (blockIdx.x * 256 + threadIdx.x) >> 5;
    const int lane = threadIdx.x & 31;
    const __nv_bfloat16* p = in + (size_t)row * HH;

    float v[3][4];
    float s = 0.f, sq = 0.f;
#pragma unroll
    for (int i = 0; i < 3; i++) {
        const uint2 raw = *(const uint2*)(p + (lane + 32 * i) * 4);
        const float2 f0 = __bfloat1622float2(*(const __nv_bfloat162*)&raw.x);
        const float2 f1 = __bfloat1622float2(*(const __nv_bfloat162*)&raw.y);
        v[i][0] = f0.x; v[i][1] = f0.y; v[i][2] = f1.x; v[i][3] = f1.y;
#pragma unroll
        for (int q = 0; q < 4; q++) { s += v[i][q]; sq += v[i][q] * v[i][q]; }
    }
#pragma unroll
    for (int off = 16; off > 0; off >>= 1) {
        s  += __shfl_xor_sync(0xffffffffu, s,  off);
        sq += __shfl_xor_sync(0xffffffffu, sq, off);
    }
    const float mu = s * (1.f / HH);
    const float rs = rsqrtf(sq * (1.f / HH) - mu * mu + 1e-5f);

    __nv_bfloat16* op = outb + (size_t)row * HH;
#pragma unroll
    for (int i = 0; i < 3; i++) {
        const int c = (lane + 32 * i) * 4;
        const float4 gv = *(const float4*)(g + c);
        const float4 bv = *(const float4*)(beta + c);
        float o0 = fmaxf(0.f, (v[i][0] - mu) * rs * gv.x + bv.x);
        float o1 = fmaxf(0.f, (v[i][1] - mu) * rs * gv.y + bv.y);
        float o2 = fmaxf(0.f, (v[i][2] - mu) * rs * gv.z + bv.z);
        float o3 = fmaxf(0.f, (v[i][3] - mu) * rs * gv.w + bv.w);
        __nv_bfloat162 p0 = __floats2bfloat162_rn(o0, o1);
        __nv_bfloat162 p1 = __floats2bfloat162_rn(o2, o3);
        uint2 u; u.x = *(uint32_t*)&p0; u.y = *(uint32_t*)&p1;
        *(uint2*)(op + c) = u;
    }
}

// ---------------------------------------------------------------------------
// Warp-per-row LayerNorm + ReLU + linear(384->1) + exp, bf16 in.
// ---------------------------------------------------------------------------
__global__ __launch_bounds__(256)
void ln_linear_exp(const __nv_bfloat16* __restrict__ in, const float* __restrict__ g,
                   const float* __restrict__ beta, const float* __restrict__ wl,
                   const float* __restrict__ bl, float* __restrict__ pred)
{
    const int row  = (blockIdx.x * 256 + threadIdx.x) >> 5;
    const int lane = threadIdx.x & 31;
    const __nv_bfloat16* p = in + (size_t)row * HH;

    float v[3][4];
    float s = 0.f, sq = 0.f;
#pragma unroll
    for (int i = 0; i < 3; i++) {
        const uint2 raw = *(const uint2*)(p + (lane + 32 * i) * 4);
        const float2 f0 = __bfloat1622float2(*(const __nv_bfloat162*)&raw.x);
        const float2 f1 = __bfloat1622float2(*(const __nv_bfloat162*)&raw.y);
        v[i][0] = f0.x; v[i][1] = f0.y; v[i][2] = f1.x; v[i][3] = f1.y;
#pragma unroll
        for (int q = 0; q < 4; q++) { s += v[i][q]; sq += v[i][q] * v[i][q]; }
    }
#pragma unroll
    for (int off = 16; off > 0; off >>= 1) {
        s  += __shfl_xor_sync(0xffffffffu, s,  off);
        sq += __shfl_xor_sync(0xffffffffu, sq, off);
    }
    const float mu = s * (1.f / HH);
    const float rs = rsqrtf(sq * (1.f / HH) - mu * mu + 1e-5f);

    float d = 0.f;
#pragma unroll
    for (int i = 0; i < 3; i++) {
        const int c = (lane + 32 * i) * 4;
        const float4 gv = *(const float4*)(g + c);
        const float4 bv = *(const float4*)(beta + c);
        const float4 wv = *(const float4*)(wl + c);
        d += fmaxf(0.f, (v[i][0] - mu) * rs * gv.x + bv.x) * wv.x;
        d += fmaxf(0.f, (v[i][1] - mu) * rs * gv.y + bv.y) * wv.y;
        d += fmaxf(0.f, (v[i][2] - mu) * rs * gv.z + bv.z) * wv.z;
        d += fmaxf(0.f, (v[i][3] - mu) * rs * gv.w + bv.w) * wv.w;
    }
#pragma unroll
    for (int off = 16; off > 0; off >>= 1)
        d += __shfl_xor_sync(0xffffffffu, d, off);
    if (lane == 0) pred[row] = expf(d + bl[0]);
}

// ---------------------------------------------------------------------------
__global__ __launch_bounds__(256)
void f32_to_bf16(const float* __restrict__ x, __nv_bfloat16* __restrict__ y)
{
    const size_t i = ((size_t)blockIdx.x * 256 + threadIdx.x) * 4;
    float4 v = *(const float4*)(x + i);
    __nv_bfloat162 p0 = __floats2bfloat162_rn(v.x, v.y);
    __nv_bfloat162 p1 = __floats2bfloat162_rn(v.z, v.w);
    uint2 o;
    o.x = *(uint32_t*)&p0; o.y = *(uint32_t*)&p1;
    *(uint2*)(y + i) = o;
}

// Wt[n][kc] = W[kc][n], fp32 -> bf16. blockIdx.y selects weight set.
__global__ __launch_bounds__(256)
void wtrans2(const float* __restrict__ w1, __nv_bfloat16* __restrict__ wt1,
             const float* __restrict__ w2, __nv_bfloat16* __restrict__ wt2)
{
    const int id = blockIdx.x * 256 + threadIdx.x;   // HH*KDIM = 442368 exact
    const int n  = id / KDIM;
    const int kc = id - n * KDIM;
    if (blockIdx.y == 0) wt1[id] = __float2bfloat16(w1[(size_t)kc * HH + n]);
    else                 wt2[id] = __float2bfloat16(w2[(size_t)kc * HH + n]);
}

// ---------------------------------------------------------------------------
__global__ __launch_bounds__(1024)
void cumsum_kernel(const int* __restrict__ dur, int* __restrict__ cum)
{
    __shared__ int buf[SS];
    const int b = blockIdx.x, tid = threadIdx.x;
    buf[tid] = dur[b * SS + tid];
    __syncthreads();
#pragma unroll
    for (int off = 1; off < SS; off <<= 1) {
        int t = buf[tid];
        int u = (tid >= off) ? buf[tid - off] : 0;
        __syncthreads();
        buf[tid] = t + u;
        __syncthreads();
    }
    cum[b * SS + tid] = buf[tid];
}

__global__ __launch_bounds__(256)
void gather_kernel(const float* __restrict__ x, const int* __restrict__ cum,
                   float* __restrict__ out)
{
    const int gw   = (blockIdx.x * 256 + threadIdx.x) >> 5;
    const int lane = threadIdx.x & 31;
    const int b = gw / MAX_OUT_T;
    const int t = gw - b * MAX_OUT_T;

    const int* c = cum + b * SS;
    const bool valid = t < c[SS - 1];
    int lo = 0, hi = SS;
    while (lo < hi) {
        int mid = (lo + hi) >> 1;
        if (c[mid] <= t) lo = mid + 1; else hi = mid;
    }
    const int src = min(lo, SS - 1);

    const float4* xin = (const float4*)(x + ((size_t)b * SS + src) * CC);
    float4* o = (float4*)(out + (size_t)gw * CC);
    const float4 z = make_float4(0.f, 0.f, 0.f, 0.f);
#pragma unroll
    for (int i = 0; i < 3; i++)
        o[lane + i * 32] = valid ? xin[lane + i * 32] : z;
}

// ---------------------------------------------------------------------------
extern "C" void kernel_launch(void* const* d_in, const int* in_sizes, int n_in,
                              void* d_out, int out_size)
{
    const float* x     = (const float*)d_in[0];
    const int*   dur   = (const int*)  d_in[1];
    const float* w1    = (const float*)d_in[2];
    const float* b1    = (const float*)d_in[3];
    const float* g1    = (const float*)d_in[4];
    const float* beta1 = (const float*)d_in[5];
    const float* w2    = (const float*)d_in[6];
    const float* b2    = (const float*)d_in[7];
    const float* g2    = (const float*)d_in[8];
    const float* beta2 = (const float*)d_in[9];
    const float* wl    = (const float*)d_in[10];
    const float* bl    = (const float*)d_in[11];
    float* out = (float*)d_out;

    __nv_bfloat16 *xb, *h1b, *wt1, *wt2, *t1b, *t2b;
    int* cum;
    cudaGetSymbolAddress((void**)&xb,   g_xb);
    cudaGetSymbolAddress((void**)&h1b,  g_h1b);
    cudaGetSymbolAddress((void**)&wt1,  g_wt1);
    cudaGetSymbolAddress((void**)&wt2,  g_wt2);
    cudaGetSymbolAddress((void**)&t1b,  g_t1b);
    cudaGetSymbolAddress((void**)&t2b,  g_t2b);
    cudaGetSymbolAddress((void**)&cum,  g_cum);

    cudaFuncSetAttribute(conv_gemm_mma, cudaFuncAttributeMaxDynamicSharedMemorySize, GEMM_SMEM);

    static cudaStream_t s2 = nullptr;
    static cudaEvent_t  ev_fork = nullptr, ev_wt = nullptr, ev_join = nullptr;
    if (s2 == nullptr) {
        cudaStreamCreateWithFlags(&s2, cudaStreamNonBlocking);
        cudaEventCreateWithFlags(&ev_fork, cudaEventDisableTiming);
        cudaEventCreateWithFlags(&ev_wt,   cudaEventDisableTiming);
        cudaEventCreateWithFlags(&ev_join, cudaEventDisableTiming);
    }

    // ---- fork: weight transpose + length regulation on s2 ------------------
    cudaEventRecord(ev_fork, (cudaStream_t)0);
    cudaStreamWaitEvent(s2, ev_fork, 0);
    {
        dim3 wg((HH * KDIM) / 256, 2);
        wtrans2<<<wg, 256, 0, s2>>>(w1, wt1, w2, wt2);
    }
    cudaEventRecord(ev_wt, s2);                       // wt1/wt2 ready marker
    cumsum_kernel<<<BB, SS, 0, s2>>>(dur, cum);
    gather_kernel<<<(BB * MAX_OUT_T) / 8, 256, 0, s2>>>(x, cum, out);
    cudaEventRecord(ev_join, s2);

    // ---- predictor chain on the main stream --------------------------------
    f32_to_bf16<<<(M_TOTAL * CC) / 1024, 256>>>(x, xb);
    cudaStreamWaitEvent((cudaStream_t)0, ev_wt, 0);   // need wt1 before GEMM1

    dim3 gemm_grid(HH / 128, M_TOTAL / 128);   // (3, 256)
    conv_gemm_mma<<<gemm_grid, 256, GEMM_SMEM>>>(xb, wt1, b1, t1b);
    ln_relu_bf16<<<M_TOTAL / 8, 256>>>(t1b, g1, beta1, h1b);
    conv_gemm_mma<<<gemm_grid, 256, GEMM_SMEM>>>(h1b, wt2, b2, t2b);
    ln_linear_exp<<<M_TOTAL / 8, 256>>>(t2b, g2, beta2, wl, bl, out + PRED_OFFSET);

    // ---- join ---------------------------------------------------------------
    cudaStreamWaitEvent((cudaStream_t)0, ev_join, 0);
}

// round 10
// speedup vs baseline: 1.2112x; 1.1460x over previous
#include <cuda_runtime.h>
#include <cuda_bf16.h>
#include <math.h>
#include <stdint.h>

#define BB 32
#define SS 1024
#define CC 384
#define HH 384
#define MAX_OUT_T 3072
#define M_TOTAL (BB*SS)          // 32768
#define M_HALF  (M_TOTAL/2)      // 16384 (multiple of SS -> halo-safe split)
#define KDIM (3*CC)              // 1152
#define PRED_OFFSET ((size_t)BB*MAX_OUT_T*CC)

// ---------------- scratch (static device globals: allocation-free) ----------
__device__ __nv_bfloat16 g_xb  [(size_t)M_TOTAL*CC];
__device__ __nv_bfloat16 g_h1b [(size_t)M_TOTAL*HH];
__device__ __nv_bfloat16 g_wt1 [(size_t)HH*KDIM];
__device__ __nv_bfloat16 g_wt2 [(size_t)HH*KDIM];
__device__ __nv_bfloat16 g_t1b [(size_t)M_TOTAL*HH];
__device__ __nv_bfloat16 g_t2b [(size_t)M_TOTAL*HH];
__device__ int   g_cum[BB*SS];

// ---------------- PTX helpers (baseline PTX only) ----------------------------
__device__ __forceinline__ uint32_t smem_u32(const void* p) {
    uint32_t a;
    asm("{ .reg .u64 t; cvta.to.shared.u64 t, %1; cvt.u32.u64 %0, t; }" : "=r"(a) : "l"(p));
    return a;
}
__device__ __forceinline__ void cp_async16(uint32_t saddr, const void* gptr, uint32_t sz) {
    asm volatile("cp.async.cg.shared.global [%0], [%1], 16, %2;"
                 :: "r"(saddr), "l"(gptr), "r"(sz) : "memory");
}
__device__ __forceinline__ void cp_commit() {
    asm volatile("cp.async.commit_group;" ::: "memory");
}
template <int N>
__device__ __forceinline__ void cp_wait() {
    asm volatile("cp.async.wait_group %0;" :: "n"(N) : "memory");
}
__device__ __forceinline__ void ldmatrix_x4(uint32_t& r0, uint32_t& r1, uint32_t& r2,
                                            uint32_t& r3, uint32_t addr) {
    asm volatile("ldmatrix.sync.aligned.m8n8.x4.shared.b16 {%0,%1,%2,%3}, [%4];"
                 : "=r"(r0), "=r"(r1), "=r"(r2), "=r"(r3) : "r"(addr));
}
__device__ __forceinline__ void mma_16816(float& d0, float& d1, float& d2, float& d3,
                                          uint32_t a0, uint32_t a1, uint32_t a2, uint32_t a3,
                                          uint32_t b0, uint32_t b1) {
    asm volatile("mma.sync.aligned.m16n8k16.row.col.f32.bf16.bf16.f32 "
                 "{%0,%1,%2,%3}, {%4,%5,%6,%7}, {%8,%9}, {%0,%1,%2,%3};"
                 : "+f"(d0), "+f"(d1), "+f"(d2), "+f"(d3)
                 : "r"(a0), "r"(a1), "r"(a2), "r"(a3), "r"(b0), "r"(b1));
}

// ---------------------------------------------------------------------------
// Conv-as-GEMM on tensor cores (mma.sync bf16), 3-stage cp.async pipeline.
// Operates on an M_HALF slice; A points at the slice base (slice is a
// multiple of SS rows, so the im2col halo logic is unchanged).
// ---------------------------------------------------------------------------
#define NSTEPS 18
#define TILE_B 16384
#define GEMM_SMEM (6*TILE_B)

__global__ __launch_bounds__(256, 2)
void conv_gemm_mma(const __nv_bfloat16* __restrict__ A,
                   const __nv_bfloat16* __restrict__ Wt,
                   const float* __restrict__ bias,
                   __nv_bfloat16* __restrict__ out)
{
    extern __shared__ __align__(1024) char smem[];
    const uint32_t sbase = smem_u32(smem);
    const int tid  = threadIdx.x;
    const int wid  = tid >> 5;
    const int lane = tid & 31;
    const int warp_m = wid & 1;
    const int warp_n = wid >> 1;
    const int n0 = blockIdx.x * 128;
    const int m0 = blockIdx.y * 128;

    const int lrow = tid >> 3;
    const int lcx  = (tid & 7) * 16;

    auto load_tiles = [&](int step, int stage) {
        const uint32_t abase = sbase + (uint32_t)stage * 2 * TILE_B;
        const uint32_t bbase = abase + TILE_B;
        const int k  = step / 6;
        const int c0 = (step - k * 6) * 64;
#pragma unroll
        for (int i = 0; i < 4; i++) {
            const int row = lrow + 32 * i;
            uint32_t off = (uint32_t)(row * 128 + lcx);
            uint32_t sw  = off ^ ((off >> 3) & 0x70);
            const int gm  = m0 + row;
            const int ss  = (gm & (SS - 1)) + k - 1;
            const bool valid = (ss >= 0) && (ss < SS);
            const char* gpa = (const char*)A + ((size_t)(gm + k - 1) * CC + c0) * 2 + lcx;
            if (!valid) gpa = (const char*)A;
            cp_async16(abase + sw, gpa, valid ? 16u : 0u);
            const char* gpb = (const char*)Wt + ((size_t)(n0 + row) * KDIM + step * 64) * 2 + lcx;
            cp_async16(bbase + sw, gpb, 16u);
        }
    };

    float acc[4][4][4];
#pragma unroll
    for (int i = 0; i < 4; i++)
#pragma unroll
        for (int j = 0; j < 4; j++)
#pragma unroll
            for (int q = 0; q < 4; q++) acc[i][j][q] = 0.f;

    const int fr_row = ((lane >> 3) & 1) * 8 + (lane & 7);
    const int fr_kb  = (lane >> 4) * 16;
    const uint32_t cxor = (uint32_t)((fr_row & 7) << 4);
    const uint32_t a_row_base = (uint32_t)((warp_m * 64 + fr_row) * 128);
    const uint32_t b_row_base = (uint32_t)((warp_n * 32 + fr_row) * 128);

    load_tiles(0, 0); cp_commit();
    load_tiles(1, 1); cp_commit();

    int stage = 0;
    for (int step = 0; step < NSTEPS; ++step) {
        cp_wait<1>();
        __syncthreads();

        {
            const int pf = stage + 2 - ((stage + 2 >= 3) ? 3 : 0);
            if (step + 2 < NSTEPS) load_tiles(step + 2, pf);
            cp_commit();
        }

        const uint32_t sa = sbase + (uint32_t)stage * 2 * TILE_B;
        const uint32_t sb = sa + TILE_B;

        uint32_t ball[4][2][4];
#pragma unroll
        for (int ks = 0; ks < 4; ks++) {
            const uint32_t col = ((uint32_t)(ks * 32 + fr_kb)) ^ cxor;
#pragma unroll
            for (int nt = 0; nt < 2; nt++) {
                const uint32_t addr = sb + b_row_base + (uint32_t)(nt * 2048) + col;
                ldmatrix_x4(ball[ks][nt][0], ball[ks][nt][1], ball[ks][nt][2], ball[ks][nt][3], addr);
            }
        }

#pragma unroll
        for (int ks = 0; ks < 4; ks++) {
            const uint32_t col = ((uint32_t)(ks * 32 + fr_kb)) ^ cxor;
            uint32_t a[4][4];
#pragma unroll
            for (int mt = 0; mt < 4; mt++) {
                const uint32_t addr = sa + a_row_base + (uint32_t)(mt * 2048) + col;
                ldmatrix_x4(a[mt][0], a[mt][1], a[mt][2], a[mt][3], addr);
            }
#pragma unroll
            for (int mt = 0; mt < 4; mt++)
#pragma unroll
                for (int nt = 0; nt < 2; nt++)
#pragma unroll
                    for (int h = 0; h < 2; h++) {
                        const int j = nt * 2 + h;
                        mma_16816(acc[mt][j][0], acc[mt][j][1], acc[mt][j][2], acc[mt][j][3],
                                  a[mt][0], a[mt][1], a[mt][2], a[mt][3],
                                  ball[ks][nt][h], ball[ks][nt][2 + h]);
                    }
        }
        stage = (stage == 2) ? 0 : stage + 1;
    }

    const int g = lane >> 2;
    const int t = lane & 3;
#pragma unroll
    for (int mt = 0; mt < 4; mt++) {
        const int row0 = m0 + warp_m * 64 + mt * 16 + g;
#pragma unroll
        for (int j = 0; j < 4; j++) {
            const int col = n0 + warp_n * 32 + j * 8 + t * 2;
            const float2 bv = *(const float2*)(bias + col);
            __nv_bfloat162 o0 = __floats2bfloat162_rn(acc[mt][j][0] + bv.x, acc[mt][j][1] + bv.y);
            __nv_bfloat162 o1 = __floats2bfloat162_rn(acc[mt][j][2] + bv.x, acc[mt][j][3] + bv.y);
            *(__nv_bfloat162*)(out + (size_t)row0 * HH + col)       = o0;
            *(__nv_bfloat162*)(out + (size_t)(row0 + 8) * HH + col) = o1;
        }
    }
}

// ---------------------------------------------------------------------------
// Warp-per-row LayerNorm + ReLU, bf16 in -> bf16 out. fp32 math.
// ---------------------------------------------------------------------------
__global__ __launch_bounds__(256)
void ln_relu_bf16(const __nv_bfloat16* __restrict__ in, const float* __restrict__ g,
                  const float* __restrict__ beta, __nv_bfloat16* __restrict__ outb)
{
    const int row  = (blockIdx.x * 256 + threadIdx.x) >> 5;
    const int lane = threadIdx.x & 31;
    const __nv_bfloat16* p = in + (size_t)row * HH;

    float v[3][4];
    float s = 0.f, sq = 0.f;
#pragma unroll
    for (int i = 0; i < 3; i++) {
        const uint2 raw = *(const uint2*)(p + (lane + 32 * i) * 4);
        const float2 f0 = __bfloat1622float2(*(const __nv_bfloat162*)&raw.x);
        const float2 f1 = __bfloat1622float2(*(const __nv_bfloat162*)&raw.y);
        v[i][0] = f0.x; v[i][1] = f0.y; v[i][2] = f1.x; v[i][3] = f1.y;
#pragma unroll
        for (int q = 0; q < 4; q++) { s += v[i][q]; sq += v[i][q] * v[i][q]; }
    }
#pragma unroll
    for (int off = 16; off > 0; off >>= 1) {
        s  += __shfl_xor_sync(0xffffffffu, s,  off);
        sq += __shfl_xor_sync(0xffffffffu, sq, off);
    }
    const float mu = s * (1.f / HH);
    const float rs = rsqrtf(sq * (1.f / HH) - mu * mu + 1e-5f);

    __nv_bfloat16* op = outb + (size_t)row * HH;
#pragma unroll
    for (int i = 0; i < 3; i++) {
        const int c = (lane + 32 * i) * 4;
        const float4 gv = *(const float4*)(g + c);
        const float4 bv = *(const float4*)(beta + c);
        float o0 = fmaxf(0.f, (v[i][0] - mu) * rs * gv.x + bv.x);
        float o1 = fmaxf(0.f, (v[i][1] - mu) * rs * gv.y + bv.y);
        float o2 = fmaxf(0.f, (v[i][2] - mu) * rs * gv.z + bv.z);
        float o3 = fmaxf(0.f, (v[i][3] - mu) * rs * gv.w + bv.w);
        __nv_bfloat162 p0 = __floats2bfloat162_rn(o0, o1);
        __nv_bfloat162 p1 = __floats2bfloat162_rn(o2, o3);
        uint2 u; u.x = *(uint32_t*)&p0; u.y = *(uint32_t*)&p1;
        *(uint2*)(op + c) = u;
    }
}

// ---------------------------------------------------------------------------
// Warp-per-row LayerNorm + ReLU + linear(384->1) + exp, bf16 in.
// ---------------------------------------------------------------------------
__global__ __launch_bounds__(256)
void ln_linear_exp(const __nv_bfloat16* __restrict__ in, const float* __restrict__ g,
                   const float* __restrict__ beta, const float* __restrict__ wl,
                   const float* __restrict__ bl, float* __restrict__ pred)
{
    const int row  = (blockIdx.x * 256 + threadIdx.x) >> 5;
    const int lane = threadIdx.x & 31;
    const __nv_bfloat16* p = in + (size_t)row * HH;

    float v[3][4];
    float s = 0.f, sq = 0.f;
#pragma unroll
    for (int i = 0; i < 3; i++) {
        const uint2 raw = *(const uint2*)(p + (lane + 32 * i) * 4);
        const float2 f0 = __bfloat1622float2(*(const __nv_bfloat162*)&raw.x);
        const float2 f1 = __bfloat1622float2(*(const __nv_bfloat162*)&raw.y);
        v[i][0] = f0.x; v[i][1] = f0.y; v[i][2] = f1.x; v[i][3] = f1.y;
#pragma unroll
        for (int q = 0; q < 4; q++) { s += v[i][q]; sq += v[i][q] * v[i][q]; }
    }
#pragma unroll
    for (int off = 16; off > 0; off >>= 1) {
        s  += __shfl_xor_sync(0xffffffffu, s,  off);
        sq += __shfl_xor_sync(0xffffffffu, sq, off);
    }
    const float mu = s * (1.f / HH);
    const float rs = rsqrtf(sq * (1.f / HH) - mu * mu + 1e-5f);

    float d = 0.f;
#pragma unroll
    for (int i = 0; i < 3; i++) {
        const int c = (lane + 32 * i) * 4;
        const float4 gv = *(const float4*)(g + c);
        const float4 bv = *(const float4*)(beta + c);
        const float4 wv = *(const float4*)(wl + c);
        d += fmaxf(0.f, (v[i][0] - mu) * rs * gv.x + bv.x) * wv.x;
        d += fmaxf(0.f, (v[i][1] - mu) * rs * gv.y + bv.y) * wv.y;
        d += fmaxf(0.f, (v[i][2] - mu) * rs * gv.z + bv.z) * wv.z;
        d += fmaxf(0.f, (v[i][3] - mu) * rs * gv.w + bv.w) * wv.w;
    }
#pragma unroll
    for (int off = 16; off > 0; off >>= 1)
        d += __shfl_xor_sync(0xffffffffu, d, off);
    if (lane == 0) pred[row] = expf(d + bl[0]);
}

// ---------------------------------------------------------------------------
__global__ __launch_bounds__(256)
void f32_to_bf16(const float* __restrict__ x, __nv_bfloat16* __restrict__ y)
{
    const size_t i = ((size_t)blockIdx.x * 256 + threadIdx.x) * 4;
    float4 v = *(const float4*)(x + i);
    __nv_bfloat162 p0 = __floats2bfloat162_rn(v.x, v.y);
    __nv_bfloat162 p1 = __floats2bfloat162_rn(v.z, v.w);
    uint2 o;
    o.x = *(uint32_t*)&p0; o.y = *(uint32_t*)&p1;
    *(uint2*)(y + i) = o;
}

__global__ __launch_bounds__(256)
void wtrans2(const float* __restrict__ w1, __nv_bfloat16* __restrict__ wt1,
             const float* __restrict__ w2, __nv_bfloat16* __restrict__ wt2)
{
    const int id = blockIdx.x * 256 + threadIdx.x;
    const int n  = id / KDIM;
    const int kc = id - n * KDIM;
    if (blockIdx.y == 0) wt1[id] = __float2bfloat16(w1[(size_t)kc * HH + n]);
    else                 wt2[id] = __float2bfloat16(w2[(size_t)kc * HH + n]);
}

// ---------------------------------------------------------------------------
__global__ __launch_bounds__(1024)
void cumsum_kernel(const int* __restrict__ dur, int* __restrict__ cum)
{
    __shared__ int buf[SS];
    const int b = blockIdx.x, tid = threadIdx.x;
    buf[tid] = dur[b * SS + tid];
    __syncthreads();
#pragma unroll
    for (int off = 1; off < SS; off <<= 1) {
        int t = buf[tid];
        int u = (tid >= off) ? buf[tid - off] : 0;
        __syncthreads();
        buf[tid] = t + u;
        __syncthreads();
    }
    cum[b * SS + tid] = buf[tid];
}

__global__ __launch_bounds__(256)
void gather_kernel(const float* __restrict__ x, const int* __restrict__ cum,
                   float* __restrict__ out)
{
    const int gw   = (blockIdx.x * 256 + threadIdx.x) >> 5;
    const int lane = threadIdx.x & 31;
    const int b = gw / MAX_OUT_T;
    const int t = gw - b * MAX_OUT_T;

    const int* c = cum + b * SS;
    const bool valid = t < c[SS - 1];
    int lo = 0, hi = SS;
    while (lo < hi) {
        int mid = (lo + hi) >> 1;
        if (c[mid] <= t) lo = mid + 1; else hi = mid;
    }
    const int src = min(lo, SS - 1);

    const float4* xin = (const float4*)(x + ((size_t)b * SS + src) * CC);
    float4* o = (float4*)(out + (size_t)gw * CC);
    const float4 z = make_float4(0.f, 0.f, 0.f, 0.f);
#pragma unroll
    for (int i = 0; i < 3; i++)
        o[lane + i * 32] = valid ? xin[lane + i * 32] : z;
}

// ---------------------------------------------------------------------------
extern "C" void kernel_launch(void* const* d_in, const int* in_sizes, int n_in,
                              void* d_out, int out_size)
{
    const float* x     = (const float*)d_in[0];
    const int*   dur   = (const int*)  d_in[1];
    const float* w1    = (const float*)d_in[2];
    const float* b1    = (const float*)d_in[3];
    const float* g1    = (const float*)d_in[4];
    const float* beta1 = (const float*)d_in[5];
    const float* w2    = (const float*)d_in[6];
    const float* b2    = (const float*)d_in[7];
    const float* g2    = (const float*)d_in[8];
    const float* beta2 = (const float*)d_in[9];
    const float* wl    = (const float*)d_in[10];
    const float* bl    = (const float*)d_in[11];
    float* out = (float*)d_out;

    __nv_bfloat16 *xb, *h1b, *wt1, *wt2, *t1b, *t2b;
    int* cum;
    cudaGetSymbolAddress((void**)&xb,   g_xb);
    cudaGetSymbolAddress((void**)&h1b,  g_h1b);
    cudaGetSymbolAddress((void**)&wt1,  g_wt1);
    cudaGetSymbolAddress((void**)&wt2,  g_wt2);
    cudaGetSymbolAddress((void**)&t1b,  g_t1b);
    cudaGetSymbolAddress((void**)&t2b,  g_t2b);
    cudaGetSymbolAddress((void**)&cum,  g_cum);

    cudaFuncSetAttribute(conv_gemm_mma, cudaFuncAttributeMaxDynamicSharedMemorySize, GEMM_SMEM);

    static cudaStream_t s2 = nullptr, s3 = nullptr;
    static cudaEvent_t  ev_fork = nullptr, ev_wt = nullptr, ev_join = nullptr, ev_s3 = nullptr;
    if (s2 == nullptr) {
        cudaStreamCreateWithFlags(&s2, cudaStreamNonBlocking);
        cudaStreamCreateWithFlags(&s3, cudaStreamNonBlocking);
        cudaEventCreateWithFlags(&ev_fork, cudaEventDisableTiming);
        cudaEventCreateWithFlags(&ev_wt,   cudaEventDisableTiming);
        cudaEventCreateWithFlags(&ev_join, cudaEventDisableTiming);
        cudaEventCreateWithFlags(&ev_s3,   cudaEventDisableTiming);
    }

    // ---- fork ---------------------------------------------------------------
    cudaEventRecord(ev_fork, (cudaStream_t)0);
    cudaStreamWaitEvent(s2, ev_fork, 0);
    cudaStreamWaitEvent(s3, ev_fork, 0);

    // ---- s2: weight transpose + length regulation ---------------------------
    {
        dim3 wg((HH * KDIM) / 256, 2);
        wtrans2<<<wg, 256, 0, s2>>>(w1, wt1, w2, wt2);
    }
    cudaEventRecord(ev_wt, s2);
    cumsum_kernel<<<BB, SS, 0, s2>>>(dur, cum);
    gather_kernel<<<(BB * MAX_OUT_T) / 8, 256, 0, s2>>>(x, cum, out);
    cudaEventRecord(ev_join, s2);

    // ---- predictor chain, split into two independent M-halves ---------------
    const dim3 half_grid(HH / 128, M_HALF / 128);   // (3, 128)
    const size_t HX = (size_t)M_HALF * CC;          // x / xb half offset
    const size_t HT = (size_t)M_HALF * HH;          // activation half offset

    // half 0 on the main stream
    f32_to_bf16<<<(M_HALF * CC) / 1024, 256>>>(x, xb);
    cudaStreamWaitEvent((cudaStream_t)0, ev_wt, 0);
    conv_gemm_mma<<<half_grid, 256, GEMM_SMEM>>>(xb, wt1, b1, t1b);
    ln_relu_bf16<<<M_HALF / 8, 256>>>(t1b, g1, beta1, h1b);
    conv_gemm_mma<<<half_grid, 256, GEMM_SMEM>>>(h1b, wt2, b2, t2b);
    ln_linear_exp<<<M_HALF / 8, 256>>>(t2b, g2, beta2, wl, bl, out + PRED_OFFSET);

    // half 1 on s3
    f32_to_bf16<<<(M_HALF * CC) / 1024, 256, 0, s3>>>(x + HX, xb + HX);
    cudaStreamWaitEvent(s3, ev_wt, 0);
    conv_gemm_mma<<<half_grid, 256, GEMM_SMEM, s3>>>(xb + HX, wt1, b1, t1b + HT);
    ln_relu_bf16<<<M_HALF / 8, 256, 0, s3>>>(t1b + HT, g1, beta1, h1b + HT);
    conv_gemm_mma<<<half_grid, 256, GEMM_SMEM, s3>>>(h1b + HT, wt2, b2, t2b + HT);
    ln_linear_exp<<<M_HALF / 8, 256, 0, s3>>>(t2b + HT, g2, beta2, wl, bl,
                                              out + PRED_OFFSET + M_HALF);
    cudaEventRecord(ev_s3, s3);

    // ---- join ----------------------------------------------------------------
    cudaStreamWaitEvent((cudaStream_t)0, ev_join, 0);
    cudaStreamWaitEvent((cudaStream_t)0, ev_s3, 0);
}

// round 12
// speedup vs baseline: 1.2308x; 1.0162x over previous
#include <cuda_runtime.h>
#include <cuda_bf16.h>
#include <math.h>
#include <stdint.h>

#define BB 32
#define SS 1024
#define CC 384
#define HH 384
#define MAX_OUT_T 3072
#define M_TOTAL (BB*SS)          // 32768
#define M_HALF  (M_TOTAL/2)      // 16384 (multiple of SS -> halo-safe split)
#define KDIM (3*CC)              // 1152
#define PRED_OFFSET ((size_t)BB*MAX_OUT_T*CC)

// ---------------- scratch (static device globals: allocation-free) ----------
__device__ __nv_bfloat16 g_xb  [(size_t)M_TOTAL*CC];
__device__ __nv_bfloat16 g_h1b [(size_t)M_TOTAL*HH];
__device__ __nv_bfloat16 g_wt1 [(size_t)HH*KDIM];
__device__ __nv_bfloat16 g_wt2 [(size_t)HH*KDIM];
__device__ __nv_bfloat16 g_t1b [(size_t)M_TOTAL*HH];
__device__ __nv_bfloat16 g_t2b [(size_t)M_TOTAL*HH];
__device__ int   g_cum[BB*SS];

// ---------------- PTX helpers (baseline PTX only) ----------------------------
__device__ __forceinline__ uint32_t smem_u32(const void* p) {
    uint32_t a;
    asm("{ .reg .u64 t; cvta.to.shared.u64 t, %1; cvt.u32.u64 %0, t; }" : "=r"(a) : "l"(p));
    return a;
}
__device__ __forceinline__ void cp_async16(uint32_t saddr, const void* gptr, uint32_t sz) {
    asm volatile("cp.async.cg.shared.global [%0], [%1], 16, %2;"
                 :: "r"(saddr), "l"(gptr), "r"(sz) : "memory");
}
__device__ __forceinline__ void cp_commit() {
    asm volatile("cp.async.commit_group;" ::: "memory");
}
template <int N>
__device__ __forceinline__ void cp_wait() {
    asm volatile("cp.async.wait_group %0;" :: "n"(N) : "memory");
}
__device__ __forceinline__ void ldmatrix_x4(uint32_t& r0, uint32_t& r1, uint32_t& r2,
                                            uint32_t& r3, uint32_t addr) {
    asm volatile("ldmatrix.sync.aligned.m8n8.x4.shared.b16 {%0,%1,%2,%3}, [%4];"
                 : "=r"(r0), "=r"(r1), "=r"(r2), "=r"(r3) : "r"(addr));
}
__device__ __forceinline__ void mma_16816(float& d0, float& d1, float& d2, float& d3,
                                          uint32_t a0, uint32_t a1, uint32_t a2, uint32_t a3,
                                          uint32_t b0, uint32_t b1) {
    asm volatile("mma.sync.aligned.m16n8k16.row.col.f32.bf16.bf16.f32 "
                 "{%0,%1,%2,%3}, {%4,%5,%6,%7}, {%8,%9}, {%0,%1,%2,%3};"
                 : "+f"(d0), "+f"(d1), "+f"(d2), "+f"(d3)
                 : "r"(a0), "r"(a1), "r"(a2), "r"(a3), "r"(b0), "r"(b1));
}

// ---------------------------------------------------------------------------
// Conv-as-GEMM with 3-tap A reuse.
//   18 MMA-steps s=(j,k), j=channel chunk 0..5, k=conv tap 0..2.
//   A: per chunk j, ONE 130-row region (x rows m0-1..m0+128, 64 ch) shared by
//      all 3 taps via +k row offset in ldmatrix addressing. Double-buffered.
//   B: one 128x64 tile per step, 4-slot ring, loaded 3 steps ahead.
//   One commit group per step; cp.async.wait_group 2.
// ---------------------------------------------------------------------------
#define NSTEPS 18
#define A_STRIDE 17408                    // 17 KB (130 rows x 128 B, padded)
#define B_BASE   (2*A_STRIDE)             // 34816
#define TILE_B   16384
#define GEMM_SMEM (B_BASE + 4*TILE_B)     // 100352 -> 2 CTAs/SM

__global__ __launch_bounds__(256, 2)
void conv_gemm_mma(const __nv_bfloat16* __restrict__ A,
                   const __nv_bfloat16* __restrict__ Wt,
                   const float* __restrict__ bias,
                   __nv_bfloat16* __restrict__ out)
{
    extern __shared__ __align__(1024) char smem[];
    const uint32_t sbase = smem_u32(smem);
    const int tid  = threadIdx.x;
    const int wid  = tid >> 5;
    const int lane = tid & 31;
    const int warp_m = wid & 1;
    const int warp_n = wid >> 1;
    const int n0 = blockIdx.x * 128;
    const int m0 = blockIdx.y * 128;

    const int lrow = tid >> 3;              // 0..31
    const int lcx  = (tid & 7) * 16;

    // A region loader: chunk j -> x rows [m0-1, m0+128], channels [64j, 64j+64)
    auto load_A = [&](int j) {
        const uint32_t abase_w = sbase + (uint32_t)((j & 1) * A_STRIDE);
        const int c0   = j * 64;
        const int seq0 = m0 & ~(SS - 1);
#pragma unroll
        for (int i = 0; i < 5; i++) {
            const int rr = lrow + 32 * i;            // 0..159
            if (rr < 130) {
                const int xr = m0 - 1 + rr;
                const bool valid = (xr >= seq0) && (xr < seq0 + SS);
                uint32_t off = (uint32_t)(rr * 128 + lcx);
                uint32_t sw  = off ^ ((off >> 3) & 0x70);
                const char* gp = valid
                    ? ((const char*)A + ((size_t)xr * CC + c0) * 2 + lcx)
                    : (const char*)A;
                cp_async16(abase_w + sw, gp, valid ? 16u : 0u);
            }
        }
    };
    // B tile loader: b = 3j+k -> Wt rows [n0, n0+128), kc0 = k*CC + 64j
    auto load_B = [&](int b) {
        const int j = b / 3, k = b - 3 * j;
        const int kc0 = k * CC + j * 64;
        const uint32_t bbase_w = sbase + B_BASE + (uint32_t)((b & 3) * TILE_B);
#pragma unroll
        for (int i = 0; i < 4; i++) {
            const int row = lrow + 32 * i;
            uint32_t off = (uint32_t)(row * 128 + lcx);
            uint32_t sw  = off ^ ((off >> 3) & 0x70);
            const char* gp = (const char*)Wt + ((size_t)(n0 + row) * KDIM + kc0) * 2 + lcx;
            cp_async16(bbase_w + sw, gp, 16u);
        }
    };

    float acc[4][4][4];
#pragma unroll
    for (int i = 0; i < 4; i++)
#pragma unroll
        for (int j = 0; j < 4; j++)
#pragma unroll
            for (int q = 0; q < 4; q++) acc[i][j][q] = 0.f;

    const int fr_row = ((lane >> 3) & 1) * 8 + (lane & 7);
    const int fr_kb  = (lane >> 4) * 16;
    const uint32_t cxor = (uint32_t)((fr_row & 7) << 4);                 // B swizzle
    const uint32_t a_row_base = (uint32_t)((warp_m * 64 + fr_row) * 128);
    const uint32_t b_row_base = (uint32_t)((warp_n * 32 + fr_row) * 128);

    // prologue: g0={A0,B0}, g1={B1}, g2={B2}
    load_A(0); load_B(0); cp_commit();
    load_B(1); cp_commit();
    load_B(2); cp_commit();

    for (int s = 0; s < NSTEPS; ++s) {
        const int j = s / 3;
        const int k = s - 3 * j;

        cp_wait<2>();            // completes groups through step s-3 (B_s, A_j ready)
        __syncthreads();         // separates prior step's reads from this step's writes

        // lookahead: B 3 steps ahead; A one chunk ahead at each chunk start
        if (s <= NSTEPS - 4) load_B(s + 3);
        if (k == 0 && j < 5)  load_A(j + 1);
        cp_commit();             // exactly one group per step (may be empty)

        const uint32_t sa = sbase + (uint32_t)((j & 1) * A_STRIDE) + (uint32_t)(k * 128);
        const uint32_t sb = sbase + B_BASE + (uint32_t)((s & 3) * TILE_B);
        const uint32_t cxork = (uint32_t)(((fr_row + k) & 7) << 4);      // A swizzle (+k rows)

        // hoist all B fragments for this step
        uint32_t ball[4][2][4];
#pragma unroll
        for (int ks = 0; ks < 4; ks++) {
            const uint32_t col = ((uint32_t)(ks * 32 + fr_kb)) ^ cxor;
#pragma unroll
            for (int nt = 0; nt < 2; nt++) {
                const uint32_t addr = sb + b_row_base + (uint32_t)(nt * 2048) + col;
                ldmatrix_x4(ball[ks][nt][0], ball[ks][nt][1], ball[ks][nt][2], ball[ks][nt][3], addr);
            }
        }

#pragma unroll
        for (int ks = 0; ks < 4; ks++) {
            const uint32_t col = ((uint32_t)(ks * 32 + fr_kb)) ^ cxork;
            uint32_t a[4][4];
#pragma unroll
            for (int mt = 0; mt < 4; mt++) {
                const uint32_t addr = sa + a_row_base + (uint32_t)(mt * 2048) + col;
                ldmatrix_x4(a[mt][0], a[mt][1], a[mt][2], a[mt][3], addr);
            }
#pragma unroll
            for (int mt = 0; mt < 4; mt++)
#pragma unroll
                for (int nt = 0; nt < 2; nt++)
#pragma unroll
                    for (int h = 0; h < 2; h++) {
                        const int jj = nt * 2 + h;
                        mma_16816(acc[mt][jj][0], acc[mt][jj][1], acc[mt][jj][2], acc[mt][jj][3],
                                  a[mt][0], a[mt][1], a[mt][2], a[mt][3],
                                  ball[ks][nt][h], ball[ks][nt][2 + h]);
                    }
        }
    }

    // ---- epilogue: bias add, bf16 stores ------------------------------------
    const int g = lane >> 2;
    const int t = lane & 3;
#pragma unroll
    for (int mt = 0; mt < 4; mt++) {
        const int row0 = m0 + warp_m * 64 + mt * 16 + g;
#pragma unroll
        for (int j = 0; j < 4; j++) {
            const int col = n0 + warp_n * 32 + j * 8 + t * 2;
            const float2 bv = *(const float2*)(bias + col);
            __nv_bfloat162 o0 = __floats2bfloat162_rn(acc[mt][j][0] + bv.x, acc[mt][j][1] + bv.y);
            __nv_bfloat162 o1 = __floats2bfloat162_rn(acc[mt][j][2] + bv.x, acc[mt][j][3] + bv.y);
            *(__nv_bfloat162*)(out + (size_t)row0 * HH + col)       = o0;
            *(__nv_bfloat162*)(out + (size_t)(row0 + 8) * HH + col) = o1;
        }
    }
}

// ---------------------------------------------------------------------------
// Warp-per-row LayerNorm + ReLU, bf16 in -> bf16 out. fp32 math.
// ---------------------------------------------------------------------------
__global__ __launch_bounds__(256)
void ln_relu_bf16(const __nv_bfloat16* __restrict__ in, const float* __restrict__ g,
                  const float* __restrict__ beta, __nv_bfloat16* __restrict__ outb)
{
    const int row  = (blockIdx.x * 256 + threadIdx.x) >> 5;
    const int lane = threadIdx.x & 31;
    const __nv_bfloat16* p = in + (size_t)row * HH;

    float v[3][4];
    float s = 0.f, sq = 0.f;
#pragma unroll
    for (int i = 0; i < 3; i++) {
        const uint2 raw = *(const uint2*)(p + (lane + 32 * i) * 4);
        const float2 f0 = __bfloat1622float2(*(const __nv_bfloat162*)&raw.x);
        const float2 f1 = __bfloat1622float2(*(const __nv_bfloat162*)&raw.y);
        v[i][0] = f0.x; v[i][1] = f0.y; v[i][2] = f1.x; v[i][3] = f1.y;
#pragma unroll
        for (int q = 0; q < 4; q++) { s += v[i][q]; sq += v[i][q] * v[i][q]; }
    }
#pragma unroll
    for (int off = 16; off > 0; off >>= 1) {
        s  += __shfl_xor_sync(0xffffffffu, s,  off);
        sq += __shfl_xor_sync(0xffffffffu, sq, off);
    }
    const float mu = s * (1.f / HH);
    const float rs = rsqrtf(sq * (1.f / HH) - mu * mu + 1e-5f);

    __nv_bfloat16* op = outb + (size_t)row * HH;
#pragma unroll
    for (int i = 0; i < 3; i++) {
        const int c = (lane + 32 * i) * 4;
        const float4 gv = *(const float4*)(g + c);
        const float4 bv = *(const float4*)(beta + c);
        float o0 = fmaxf(0.f, (v[i][0] - mu) * rs * gv.x + bv.x);
        float o1 = fmaxf(0.f, (v[i][1] - mu) * rs * gv.y + bv.y);
        float o2 = fmaxf(0.f, (v[i][2] - mu) * rs * gv.z + bv.z);
        float o3 = fmaxf(0.f, (v[i][3] - mu) * rs * gv.w + bv.w);
        __nv_bfloat162 p0 = __floats2bfloat162_rn(o0, o1);
        __nv_bfloat162 p1 = __floats2bfloat162_rn(o2, o3);
        uint2 u; u.x = *(uint32_t*)&p0; u.y = *(uint32_t*)&p1;
        *(uint2*)(op + c) = u;
    }
}

// ---------------------------------------------------------------------------
// Warp-per-row LayerNorm + ReLU + linear(384->1) + exp, bf16 in.
// ---------------------------------------------------------------------------
__global__ __launch_bounds__(256)
void ln_linear_exp(const __nv_bfloat16* __restrict__ in, const float* __restrict__ g,
                   const float* __restrict__ beta, const float* __restrict__ wl,
                   const float* __restrict__ bl, float* __restrict__ pred)
{
    const int row  = (blockIdx.x * 256 + threadIdx.x) >> 5;
    const int lane = threadIdx.x & 31;
    const __nv_bfloat16* p = in + (size_t)row * HH;

    float v[3][4];
    float s = 0.f, sq = 0.f;
#pragma unroll
    for (int i = 0; i < 3; i++) {
        const uint2 raw = *(const uint2*)(p + (lane + 32 * i) * 4);
        const float2 f0 = __bfloat1622float2(*(const __nv_bfloat162*)&raw.x);
        const float2 f1 = __bfloat1622float2(*(const __nv_bfloat162*)&raw.y);
        v[i][0] = f0.x; v[i][1] = f0.y; v[i][2] = f1.x; v[i][3] = f1.y;
#pragma unroll
        for (int q = 0; q < 4; q++) { s += v[i][q]; sq += v[i][q] * v[i][q]; }
    }
#pragma unroll
    for (int off = 16; off > 0; off >>= 1) {
        s  += __shfl_xor_sync(0xffffffffu, s,  off);
        sq += __shfl_xor_sync(0xffffffffu, sq, off);
    }
    const float mu = s * (1.f / HH);
    const float rs = rsqrtf(sq * (1.f / HH) - mu * mu + 1e-5f);

    float d = 0.f;
#pragma unroll
    for (int i = 0; i < 3; i++) {
        const int c = (lane + 32 * i) * 4;
        const float4 gv = *(const float4*)(g + c);
        const float4 bv = *(const float4*)(beta + c);
        const float4 wv = *(const float4*)(wl + c);
        d += fmaxf(0.f, (v[i][0] - mu) * rs * gv.x + bv.x) * wv.x;
        d += fmaxf(0.f, (v[i][1] - mu) * rs * gv.y + bv.y) * wv.y;
        d += fmaxf(0.f, (v[i][2] - mu) * rs * gv.z + bv.z) * wv.z;
        d += fmaxf(0.f, (v[i][3] - mu) * rs * gv.w + bv.w) * wv.w;
    }
#pragma unroll
    for (int off = 16; off > 0; off >>= 1)
        d += __shfl_xor_sync(0xffffffffu, d, off);
    if (lane == 0) pred[row] = expf(d + bl[0]);
}

// ---------------------------------------------------------------------------
__global__ __launch_bounds__(256)
void f32_to_bf16(const float* __restrict__ x, __nv_bfloat16* __restrict__ y)
{
    const size_t i = ((size_t)blockIdx.x * 256 + threadIdx.x) * 4;
    float4 v = *(const float4*)(x + i);
    __nv_bfloat162 p0 = __floats2bfloat162_rn(v.x, v.y);
    __nv_bfloat162 p1 = __floats2bfloat162_rn(v.z, v.w);
    uint2 o;
    o.x = *(uint32_t*)&p0; o.y = *(uint32_t*)&p1;
    *(uint2*)(y + i) = o;
}

__global__ __launch_bounds__(256)
void wtrans2(const float* __restrict__ w1, __nv_bfloat16* __restrict__ wt1,
             const float* __restrict__ w2, __nv_bfloat16* __restrict__ wt2)
{
    const int id = blockIdx.x * 256 + threadIdx.x;
    const int n  = id / KDIM;
    const int kc = id - n * KDIM;
    if (blockIdx.y == 0) wt1[id] = __float2bfloat16(w1[(size_t)kc * HH + n]);
    else                 wt2[id] = __float2bfloat16(w2[(size_t)kc * HH + n]);
}

// ---------------------------------------------------------------------------
__global__ __launch_bounds__(1024)
void cumsum_kernel(const int* __restrict__ dur, int* __restrict__ cum)
{
    __shared__ int buf[SS];
    const int b = blockIdx.x, tid = threadIdx.x;
    buf[tid] = dur[b * SS + tid];
    __syncthreads();
#pragma unroll
    for (int off = 1; off < SS; off <<= 1) {
        int t = buf[tid];
        int u = (tid >= off) ? buf[tid - off] : 0;
        __syncthreads();
        buf[tid] = t + u;
        __syncthreads();
    }
    cum[b * SS + tid] = buf[tid];
}

__global__ __launch_bounds__(256)
void gather_kernel(const float* __restrict__ x, const int* __restrict__ cum,
                   float* __restrict__ out)
{
    const int gw   = (blockIdx.x * 256 + threadIdx.x) >> 5;
    const int lane = threadIdx.x & 31;
    const int b = gw / MAX_OUT_T;
    const int t = gw - b * MAX_OUT_T;

    const int* c = cum + b * SS;
    const bool valid = t < c[SS - 1];
    int lo = 0, hi = SS;
    while (lo < hi) {
        int mid = (lo + hi) >> 1;
        if (c[mid] <= t) lo = mid + 1; else hi = mid;
    }
    const int src = min(lo, SS - 1);

    const float4* xin = (const float4*)(x + ((size_t)b * SS + src) * CC);
    float4* o = (float4*)(out + (size_t)gw * CC);
    const float4 z = make_float4(0.f, 0.f, 0.f, 0.f);
#pragma unroll
    for (int i = 0; i < 3; i++)
        o[lane + i * 32] = valid ? xin[lane + i * 32] : z;
}

// ---------------------------------------------------------------------------
extern "C" void kernel_launch(void* const* d_in, const int* in_sizes, int n_in,
                              void* d_out, int out_size)
{
    const float* x     = (const float*)d_in[0];
    const int*   dur   = (const int*)  d_in[1];
    const float* w1    = (const float*)d_in[2];
    const float* b1    = (const float*)d_in[3];
    const float* g1    = (const float*)d_in[4];
    const float* beta1 = (const float*)d_in[5];
    const float* w2    = (const float*)d_in[6];
    const float* b2    = (const float*)d_in[7];
    const float* g2    = (const float*)d_in[8];
    const float* beta2 = (const float*)d_in[9];
    const float* wl    = (const float*)d_in[10];
    const float* bl    = (const float*)d_in[11];
    float* out = (float*)d_out;

    __nv_bfloat16 *xb, *h1b, *wt1, *wt2, *t1b, *t2b;
    int* cum;
    cudaGetSymbolAddress((void**)&xb,   g_xb);
    cudaGetSymbolAddress((void**)&h1b,  g_h1b);
    cudaGetSymbolAddress((void**)&wt1,  g_wt1);
    cudaGetSymbolAddress((void**)&wt2,  g_wt2);
    cudaGetSymbolAddress((void**)&t1b,  g_t1b);
    cudaGetSymbolAddress((void**)&t2b,  g_t2b);
    cudaGetSymbolAddress((void**)&cum,  g_cum);

    cudaFuncSetAttribute(conv_gemm_mma, cudaFuncAttributeMaxDynamicSharedMemorySize, GEMM_SMEM);

    static cudaStream_t s2 = nullptr, s3 = nullptr;
    static cudaEvent_t  ev_fork = nullptr, ev_wt = nullptr, ev_join = nullptr, ev_s3 = nullptr;
    if (s2 == nullptr) {
        cudaStreamCreateWithFlags(&s2, cudaStreamNonBlocking);
        cudaStreamCreateWithFlags(&s3, cudaStreamNonBlocking);
        cudaEventCreateWithFlags(&ev_fork, cudaEventDisableTiming);
        cudaEventCreateWithFlags(&ev_wt,   cudaEventDisableTiming);
        cudaEventCreateWithFlags(&ev_join, cudaEventDisableTiming);
        cudaEventCreateWithFlags(&ev_s3,   cudaEventDisableTiming);
    }

    // ---- fork ---------------------------------------------------------------
    cudaEventRecord(ev_fork, (cudaStream_t)0);
    cudaStreamWaitEvent(s2, ev_fork, 0);
    cudaStreamWaitEvent(s3, ev_fork, 0);

    // ---- s2: weight transpose + length regulation ---------------------------
    {
        dim3 wg((HH * KDIM) / 256, 2);
        wtrans2<<<wg, 256, 0, s2>>>(w1, wt1, w2, wt2);
    }
    cudaEventRecord(ev_wt, s2);
    cumsum_kernel<<<BB, SS, 0, s2>>>(dur, cum);
    gather_kernel<<<(BB * MAX_OUT_T) / 8, 256, 0, s2>>>(x, cum, out);
    cudaEventRecord(ev_join, s2);

    // ---- predictor chain, split into two independent M-halves ---------------
    const dim3 half_grid(HH / 128, M_HALF / 128);   // (3, 128)
    const size_t HX = (size_t)M_HALF * CC;
    const size_t HT = (size_t)M_HALF * HH;

    // half 0 on the main stream
    f32_to_bf16<<<(M_HALF * CC) / 1024, 256>>>(x, xb);
    cudaStreamWaitEvent((cudaStream_t)0, ev_wt, 0);
    conv_gemm_mma<<<half_grid, 256, GEMM_SMEM>>>(xb, wt1, b1, t1b);
    ln_relu_bf16<<<M_HALF / 8, 256>>>(t1b, g1, beta1, h1b);
    conv_gemm_mma<<<half_grid, 256, GEMM_SMEM>>>(h1b, wt2, b2, t2b);
    ln_linear_exp<<<M_HALF / 8, 256>>>(t2b, g2, beta2, wl, bl, out + PRED_OFFSET);

    // half 1 on s3
    f32_to_bf16<<<(M_HALF * CC) / 1024, 256, 0, s3>>>(x + HX, xb + HX);
    cudaStreamWaitEvent(s3, ev_wt, 0);
    conv_gemm_mma<<<half_grid, 256, GEMM_SMEM, s3>>>(xb + HX, wt1, b1, t1b + HT);
    ln_relu_bf16<<<M_HALF / 8, 256, 0, s3>>>(t1b + HT, g1, beta1, h1b + HT);
    conv_gemm_mma<<<half_grid, 256, GEMM_SMEM, s3>>>(h1b + HT, wt2, b2, t2b + HT);
    ln_linear_exp<<<M_HALF / 8, 256, 0, s3>>>(t2b + HT, g2, beta2, wl, bl,
                                              out + PRED_OFFSET + M_HALF);
    cudaEventRecord(ev_s3, s3);

    // ---- join ----------------------------------------------------------------
    cudaStreamWaitEvent((cudaStream_t)0, ev_join, 0);
    cudaStreamWaitEvent((cudaStream_t)0, ev_s3, 0);
}